// round 2
// baseline (speedup 1.0000x reference)
#include <cuda_runtime.h>
#include <math.h>

// Problem constants
#define BB 32
#define TT 2048
#define PP 128
#define KK 256
#define RR 8
#define MM 64
#define CCH 410            // number of independent 5-step chunks = ceil(T/5)
#define NR (BB*CCH)        // 13120 state rows (all chunks x batch, independent)
#define NROWS (BB*TT)      // 65536 encoder rows

// Scratch (no cudaMalloc allowed -> device globals)
__device__ float g_bufA[NROWS*KK];
__device__ float g_bufB[NROWS*KK];
__device__ float g_xseq[NROWS*KK];
__device__ float g_X[NR*KK];
__device__ float g_Z[NR*MM];
__device__ float g_Hs[NR*KK];

// ---------------------------------------------------------------------------
// GEMM: C = tanh(A @ W^T + bias)
// A: M x Kd row-major, W: N x Kd row-major (both K-contiguous), bias: N
// mode 0: C row r at C + r*ldc
// mode 1: scatter: r -> (b = r/CCH, c = r%CCH, t = 5c+step); row written to
//         C + (b*T + t)*ldc, skipped if t >= T.
// Tiling: 64x64x16, 256 threads, 4x4 microtile. M%64==0, N%64==0, Kd%16==0
// for every launch in this problem, so no bounds checks.
// ---------------------------------------------------------------------------
__global__ void __launch_bounds__(256)
gemm_tanh_kernel(const float* __restrict__ A, const float* __restrict__ W,
                 const float* __restrict__ bias, float* __restrict__ C,
                 int M, int N, int Kd, int ldc, int mode, int step)
{
    __shared__ float As[16][64];
    __shared__ float Ws[16][64];
    const int tid = threadIdx.x;
    const int row0 = blockIdx.y * 64;
    const int col0 = blockIdx.x * 64;
    const int ty = tid / 16, tx = tid % 16;
    const int lk = tid % 16;   // k within tile
    const int lr = tid / 16;   // row within tile (stride 16)

    float acc[4][4] = {};

    for (int k0 = 0; k0 < Kd; k0 += 16) {
        #pragma unroll
        for (int i = 0; i < 4; i++) {
            As[lk][lr + 16*i] = A[(size_t)(row0 + lr + 16*i) * Kd + k0 + lk];
            Ws[lk][lr + 16*i] = W[(size_t)(col0 + lr + 16*i) * Kd + k0 + lk];
        }
        __syncthreads();
        #pragma unroll
        for (int k = 0; k < 16; k++) {
            float ra[4], rb[4];
            #pragma unroll
            for (int i = 0; i < 4; i++) ra[i] = As[k][ty*4 + i];
            #pragma unroll
            for (int j = 0; j < 4; j++) rb[j] = Ws[k][tx*4 + j];
            #pragma unroll
            for (int i = 0; i < 4; i++)
                #pragma unroll
                for (int j = 0; j < 4; j++)
                    acc[i][j] = fmaf(ra[i], rb[j], acc[i][j]);
        }
        __syncthreads();
    }

    #pragma unroll
    for (int i = 0; i < 4; i++) {
        int r = row0 + ty*4 + i;
        float* crow;
        if (mode == 0) {
            crow = C + (size_t)r * ldc;
        } else {
            int b = r / CCH, c = r % CCH;
            int t = 5*c + step;
            if (t >= TT) continue;
            crow = C + ((size_t)b * TT + t) * ldc;
        }
        #pragma unroll
        for (int j = 0; j < 4; j++) {
            int cix = col0 + tx*4 + j;
            crow[cix] = tanhf(acc[i][j] + bias[cix]);
        }
    }
}

// ---------------------------------------------------------------------------
// Gather chunk-start states: X[r] = x_seq[b, 5c], Z[r] = z_seq[b, 5c]
// ---------------------------------------------------------------------------
__global__ void gather_kernel(const float* __restrict__ xseq,
                              const float* __restrict__ zseq,
                              float* __restrict__ X, float* __restrict__ Z)
{
    int r = blockIdx.x;
    int b = r / CCH, c = r % CCH;
    int t0 = 5 * c;
    int tid = threadIdx.x;
    X[(size_t)r*KK + tid] = xseq[((size_t)b*TT + t0)*KK + tid];
    if (tid < MM)
        Z[(size_t)r*MM + tid] = zseq[((size_t)b*TT + t0)*MM + tid];
}

// ---------------------------------------------------------------------------
// One recurrent sub-step for all NR rows. Warp-per-row; 8 rows per block.
//  z' = z + (tanh(z)@Wz^T - z)/100
//  s  = sigmoid(z' @ Az^T + Az_b)
//  x' = x + (((tanh(x)@L) * s)@Rm^T - x)/100
// Writes z' into z_pred at (b, t=5c+step) when t<T, and updates X, Z state.
// ---------------------------------------------------------------------------
__global__ void __launch_bounds__(256)
step_kernel(const float* __restrict__ Wz, const float* __restrict__ Azw,
            const float* __restrict__ Azb, const float* __restrict__ Lw,
            const float* __restrict__ Rw,
            float* __restrict__ X, float* __restrict__ Z,
            float* __restrict__ zpred, int step)
{
    __shared__ float sWz[64*64];   // 16 KB
    __shared__ float sAz[8*64];    // 2 KB
    __shared__ float sAzb[8];
    __shared__ float sL[256*8];    // 8 KB   (K x R, row-major)
    __shared__ float sR[256*8];    // 8 KB   (K x R, row-major)
    __shared__ float stz[8][64];   // per-warp tanh(z) then z'
    __shared__ float stx[8][256];  // per-warp tanh(x)
    __shared__ float su[8][8];     // per-warp gated u

    const int tid = threadIdx.x;
    for (int i = tid; i < 64*64; i += 256) sWz[i] = Wz[i];
    for (int i = tid; i < 8*64;  i += 256) sAz[i] = Azw[i];
    if (tid < 8) sAzb[tid] = Azb[tid];
    for (int i = tid; i < 256*8; i += 256) { sL[i] = Lw[i]; sR[i] = Rw[i]; }
    __syncthreads();

    const int w = tid / 32, lane = tid % 32;
    const int r = blockIdx.x * 8 + w;
    const int b = r / CCH, c = r % CCH;
    const int t = 5*c + step;

    float zv[2], xv[8];
    #pragma unroll
    for (int k = 0; k < 2; k++) zv[k] = Z[(size_t)r*MM + lane + 32*k];
    #pragma unroll
    for (int k = 0; k < 8; k++) xv[k] = X[(size_t)r*KK + lane + 32*k];

    #pragma unroll
    for (int k = 0; k < 2; k++) stz[w][lane + 32*k] = tanhf(zv[k]);
    #pragma unroll
    for (int k = 0; k < 8; k++) stx[w][lane + 32*k] = tanhf(xv[k]);
    __syncwarp();

    // z update
    float znew[2];
    #pragma unroll
    for (int k = 0; k < 2; k++) {
        int j = lane + 32*k;
        float acc = 0.f;
        #pragma unroll 8
        for (int i = 0; i < 64; i++) acc = fmaf(stz[w][i], sWz[j*64 + i], acc);
        znew[k] = zv[k] + (acc - zv[k]) * 0.01f;
    }
    __syncwarp();
    #pragma unroll
    for (int k = 0; k < 2; k++) stz[w][lane + 32*k] = znew[k];  // z' for gate
    __syncwarp();

    // gate + u (lanes 0..7, one per rank-R component)
    if (lane < 8) {
        float ga = 0.f;
        #pragma unroll 8
        for (int i = 0; i < 64; i++) ga = fmaf(stz[w][i], sAz[lane*64 + i], ga);
        float sg = 1.f / (1.f + expf(-(ga + sAzb[lane])));
        float ua = 0.f;
        #pragma unroll 8
        for (int i = 0; i < 256; i++) ua = fmaf(stx[w][i], sL[i*8 + lane], ua);
        su[w][lane] = ua * sg;
    }
    __syncwarp();

    float uu[8];
    #pragma unroll
    for (int i = 0; i < 8; i++) uu[i] = su[w][i];

    // x update
    #pragma unroll
    for (int k = 0; k < 8; k++) {
        int j = lane + 32*k;
        float acc = 0.f;
        #pragma unroll
        for (int i = 0; i < 8; i++) acc = fmaf(uu[i], sR[j*8 + i], acc);
        X[(size_t)r*KK + j] = xv[k] + (acc - xv[k]) * 0.01f;
    }

    #pragma unroll
    for (int k = 0; k < 2; k++) {
        Z[(size_t)r*MM + lane + 32*k] = znew[k];
        if (t < TT)
            zpred[((size_t)b*TT + t)*MM + lane + 32*k] = znew[k];
    }
}

// ---------------------------------------------------------------------------
extern "C" void kernel_launch(void* const* d_in, const int* in_sizes, int n_in,
                              void* d_out, int out_size)
{
    (void)in_sizes; (void)n_in; (void)out_size;
    const float* in_seq = (const float*)d_in[0];
    const float* L      = (const float*)d_in[1];
    const float* Rm     = (const float*)d_in[2];
    const float* Wz     = (const float*)d_in[3];
    const float* Az_w   = (const float*)d_in[4];
    const float* Az_b   = (const float*)d_in[5];
    const float* ex1_w  = (const float*)d_in[6];
    const float* ex1_b  = (const float*)d_in[7];
    const float* ex2_w  = (const float*)d_in[8];
    const float* ex2_b  = (const float*)d_in[9];
    const float* ex3_w  = (const float*)d_in[10];
    const float* ex3_b  = (const float*)d_in[11];
    const float* ez1_w  = (const float*)d_in[12];
    const float* ez1_b  = (const float*)d_in[13];
    const float* ez2_w  = (const float*)d_in[14];
    const float* ez2_b  = (const float*)d_in[15];
    const float* ez3_w  = (const float*)d_in[16];
    const float* ez3_b  = (const float*)d_in[17];
    const float* de1_w  = (const float*)d_in[18];
    const float* de1_b  = (const float*)d_in[19];
    const float* de2_w  = (const float*)d_in[20];
    const float* de2_b  = (const float*)d_in[21];

    float* out    = (float*)d_out;
    float* x_pred = out;
    float* x_rec  = out + (size_t)BB*TT*PP;
    float* z_pred = out + 2*(size_t)BB*TT*PP;
    float* z_seq  = z_pred + (size_t)BB*TT*MM;

    float *bufA, *bufB, *xseq, *Xs, *Zs, *Hs;
    cudaGetSymbolAddress((void**)&bufA, g_bufA);
    cudaGetSymbolAddress((void**)&bufB, g_bufB);
    cudaGetSymbolAddress((void**)&xseq, g_xseq);
    cudaGetSymbolAddress((void**)&Xs,   g_X);
    cudaGetSymbolAddress((void**)&Zs,   g_Z);
    cudaGetSymbolAddress((void**)&Hs,   g_Hs);

    #define GEMM(A, W, Bv, C, M, N, K, ldc, mode, step)                         \
        gemm_tanh_kernel<<<dim3((N)/64, (M)/64), 256>>>(A, W, Bv, C, M, N, K,   \
                                                        ldc, mode, step)

    // Encoders
    GEMM(in_seq, ex1_w, ex1_b, bufA, NROWS, KK, PP, KK, 0, 0);
    GEMM(bufA,   ex2_w, ex2_b, bufB, NROWS, KK, KK, KK, 0, 0);
    GEMM(bufB,   ex3_w, ex3_b, xseq, NROWS, KK, KK, KK, 0, 0);
    GEMM(in_seq, ez1_w, ez1_b, bufA, NROWS, MM, PP, MM, 0, 0);
    GEMM(bufA,   ez2_w, ez2_b, bufB, NROWS, MM, MM, MM, 0, 0);
    GEMM(bufB,   ez3_w, ez3_b, z_seq, NROWS, MM, MM, MM, 0, 0);

    // x_recon = dec(x_seq)
    GEMM(xseq, de1_w, de1_b, bufA,  NROWS, KK, KK, KK, 0, 0);
    GEMM(bufA, de2_w, de2_b, x_rec, NROWS, PP, KK, PP, 0, 0);

    // Chunk-start states
    gather_kernel<<<NR, 256>>>(xseq, z_seq, Xs, Zs);

    // 5 global sub-steps over all 13120 independent rows
    for (int s = 0; s < 5; s++) {
        step_kernel<<<NR/8, 256>>>(Wz, Az_w, Az_b, L, Rm, Xs, Zs, z_pred, s);
        GEMM(Xs, de1_w, de1_b, Hs, NR, KK, KK, KK, 0, 0);
        GEMM(Hs, de2_w, de2_b, x_pred, NR, PP, KK, PP, 1, s);
    }
    #undef GEMM
}

// round 3
// speedup vs baseline: 3.1165x; 3.1165x over previous
#include <cuda_runtime.h>
#include <cuda_fp16.h>
#include <math.h>
#include <stdint.h>

// Problem constants
#define BB 32
#define TT 2048
#define PP 128
#define KK 256
#define RR 8
#define MM 64
#define CCH 410            // independent 5-step chunks = ceil(T/5)
#define NR (BB*CCH)        // 13120 state rows
#define NRP 13184          // NR padded to multiple of 128 (103*128)
#define NROWS (BB*TT)      // 65536 encoder rows

// Scratch (no cudaMalloc allowed -> device globals; zero-initialized)
__device__ float g_bufA[NROWS*KK];
__device__ float g_bufB[NROWS*KK];
__device__ float g_xseq[NROWS*KK];
__device__ float g_X[NRP*KK];      // pad rows [NR,NRP) stay 0 forever
__device__ float g_Z[NR*MM];
__device__ float g_Hs[NRP*KK];

// ---------------------------------------------------------------------------
// helpers
// ---------------------------------------------------------------------------
__device__ __forceinline__ uint4 pack8(float4 a, float4 b) {
    __half2 h0 = __floats2half2_rn(a.x, a.y);
    __half2 h1 = __floats2half2_rn(a.z, a.w);
    __half2 h2 = __floats2half2_rn(b.x, b.y);
    __half2 h3 = __floats2half2_rn(b.z, b.w);
    uint4 u;
    u.x = *reinterpret_cast<unsigned*>(&h0);
    u.y = *reinterpret_cast<unsigned*>(&h1);
    u.z = *reinterpret_cast<unsigned*>(&h2);
    u.w = *reinterpret_cast<unsigned*>(&h3);
    return u;
}

__device__ __forceinline__ void ldsm4(uint32_t* r, uint32_t addr) {
    asm volatile("ldmatrix.sync.aligned.m8n8.x4.shared.b16 {%0,%1,%2,%3}, [%4];\n"
        : "=r"(r[0]), "=r"(r[1]), "=r"(r[2]), "=r"(r[3]) : "r"(addr));
}

__device__ __forceinline__ void mma16816(float* c, const uint32_t* a,
                                         uint32_t b0, uint32_t b1) {
    asm volatile(
      "mma.sync.aligned.m16n8k16.row.col.f32.f16.f16.f32 "
      "{%0,%1,%2,%3}, {%4,%5,%6,%7}, {%8,%9}, {%0,%1,%2,%3};\n"
      : "+f"(c[0]), "+f"(c[1]), "+f"(c[2]), "+f"(c[3])
      : "r"(a[0]), "r"(a[1]), "r"(a[2]), "r"(a[3]), "r"(b0), "r"(b1));
}

// ---------------------------------------------------------------------------
// Tensor-core GEMM: C = tanh(A @ W^T + bias)
// A: Mx x Kd row-major fp32, W: N x Kd row-major fp32 (k-contiguous), bias: N.
// fp32 -> fp16 conversion fused into smem staging; fp32 accumulate.
// Block tile 128 x BN x 32. 8 warps: 4 (m) x 2 (n); warp tile 32 x BN/2.
// mode 0: C row r at C + r*ldc
// mode 1: scatter r -> (b=r/CCH, c=r%CCH, t=5c+step) into C + (b*T+t)*ldc,
//         skipped when r >= NR or t >= T.
// Requires: Mx % 128 == 0, N % BN == 0, Kd % 32 == 0.
// ---------------------------------------------------------------------------
template<int BN>
__global__ void __launch_bounds__(256, 2)
gemm_hmma(const float* __restrict__ A, const float* __restrict__ W,
          const float* __restrict__ bias, float* __restrict__ C,
          int Kd, int ldc, int mode, int step)
{
    constexpr int BM = 128;
    constexpr int BK = 32;              // k per stage (fp16 elems == fp32 elems)
    constexpr int WN = BN / 2;          // cols per warp
    constexpr int NT = WN / 8;          // n8 tiles per warp (8 or 4)
    constexpr int PITCH = 40;           // halfs per smem row (32 + 8 pad)

    __shared__ __align__(16) __half sA[2][BM * PITCH];
    __shared__ __align__(16) __half sB[2][BN * PITCH];

    const int tid  = threadIdx.x;
    const int lane = tid & 31;
    const int wid  = tid >> 5;
    const int wm   = wid & 3;           // warp row block (32 rows each)
    const int wn   = wid >> 2;          // warp col block (WN cols each)
    const int row0 = blockIdx.y * BM;
    const int col0 = blockIdx.x * BN;

    // staging mapping: thread -> (row ar, 16-float segment aseg)
    const int ar   = tid >> 1;          // 0..127
    const int aseg = (tid & 1) << 4;    // 0 or 16

    const float4* gA4 = reinterpret_cast<const float4*>(
        A + (size_t)(row0 + ar) * Kd + aseg);
    const float4* gB4 = reinterpret_cast<const float4*>(
        W + (size_t)(col0 + ar) * Kd + aseg);

    // ldmatrix lane address components
    const int arow  = wm * 32 + (lane & 15);
    const int akoff = (lane >> 4) << 3;
    const int brow  = wn * WN + (lane & 7) + ((lane >> 4) << 3);
    const int bkoff = ((lane >> 3) & 1) << 3;

    float acc[2][NT][4];
    #pragma unroll
    for (int i = 0; i < 2; i++)
        #pragma unroll
        for (int j = 0; j < NT; j++)
            #pragma unroll
            for (int q = 0; q < 4; q++) acc[i][j][q] = 0.f;

    const int S = Kd / BK;

    uint4 pa0, pa1, pb0, pb1;
    // ---- prologue: load stage 0 ----
    {
        const float4* p = gA4;
        float4 v0 = p[0], v1 = p[1], v2 = p[2], v3 = p[3];
        pa0 = pack8(v0, v1); pa1 = pack8(v2, v3);
        if (BN == 128 || tid < 128) {
            const float4* q = gB4;
            float4 w0 = q[0], w1 = q[1], w2 = q[2], w3 = q[3];
            pb0 = pack8(w0, w1); pb1 = pack8(w2, w3);
        }
        *reinterpret_cast<uint4*>(&sA[0][ar * PITCH + aseg])     = pa0;
        *reinterpret_cast<uint4*>(&sA[0][ar * PITCH + aseg + 8]) = pa1;
        if (BN == 128 || tid < 128) {
            *reinterpret_cast<uint4*>(&sB[0][ar * PITCH + aseg])     = pb0;
            *reinterpret_cast<uint4*>(&sB[0][ar * PITCH + aseg + 8]) = pb1;
        }
    }
    __syncthreads();

    for (int s = 0; s < S; s++) {
        const int cur = s & 1;
        const bool hasNext = (s + 1 < S);
        if (hasNext) {
            const float4* p = gA4 + (size_t)(s + 1) * (BK / 4);
            float4 v0 = p[0], v1 = p[1], v2 = p[2], v3 = p[3];
            pa0 = pack8(v0, v1); pa1 = pack8(v2, v3);
            if (BN == 128 || tid < 128) {
                const float4* q = gB4 + (size_t)(s + 1) * (BK / 4);
                float4 w0 = q[0], w1 = q[1], w2 = q[2], w3 = q[3];
                pb0 = pack8(w0, w1); pb1 = pack8(w2, w3);
            }
        }

        const uint32_t baseA = (uint32_t)__cvta_generic_to_shared(&sA[cur][0]);
        const uint32_t baseB = (uint32_t)__cvta_generic_to_shared(&sB[cur][0]);

        #pragma unroll
        for (int kk = 0; kk < BK; kk += 16) {
            uint32_t afrag[2][4];
            uint32_t aAddr = baseA + (uint32_t)((arow * PITCH + kk + akoff) * 2);
            ldsm4(afrag[0], aAddr);
            ldsm4(afrag[1], aAddr + 16 * PITCH * 2);
            #pragma unroll
            for (int j2 = 0; j2 < NT / 2; j2++) {
                uint32_t bfrag[4];
                ldsm4(bfrag, baseB + (uint32_t)(((brow + j2 * 16) * PITCH + kk + bkoff) * 2));
                mma16816(acc[0][2 * j2],     afrag[0], bfrag[0], bfrag[1]);
                mma16816(acc[0][2 * j2 + 1], afrag[0], bfrag[2], bfrag[3]);
                mma16816(acc[1][2 * j2],     afrag[1], bfrag[0], bfrag[1]);
                mma16816(acc[1][2 * j2 + 1], afrag[1], bfrag[2], bfrag[3]);
            }
        }

        if (hasNext) {
            const int nxt = cur ^ 1;
            *reinterpret_cast<uint4*>(&sA[nxt][ar * PITCH + aseg])     = pa0;
            *reinterpret_cast<uint4*>(&sA[nxt][ar * PITCH + aseg + 8]) = pa1;
            if (BN == 128 || tid < 128) {
                *reinterpret_cast<uint4*>(&sB[nxt][ar * PITCH + aseg])     = pb0;
                *reinterpret_cast<uint4*>(&sB[nxt][ar * PITCH + aseg + 8]) = pb1;
            }
            __syncthreads();
        }
    }

    // ---- epilogue: bias + tanh ----
    const int g  = lane >> 2;
    const int cq = (lane & 3) << 1;
    #pragma unroll
    for (int i = 0; i < 2; i++) {
        #pragma unroll
        for (int h = 0; h < 2; h++) {
            int r = row0 + wm * 32 + i * 16 + h * 8 + g;
            float* crow;
            if (mode == 0) {
                crow = C + (size_t)r * ldc;
            } else {
                if (r >= NR) continue;
                int b = r / CCH, c = r % CCH;
                int t = 5 * c + step;
                if (t >= TT) continue;
                crow = C + ((size_t)b * TT + t) * ldc;
            }
            #pragma unroll
            for (int nt = 0; nt < NT; nt++) {
                int col = col0 + wn * WN + nt * 8 + cq;
                float2 o;
                o.x = tanhf(acc[i][nt][2 * h + 0] + __ldg(bias + col));
                o.y = tanhf(acc[i][nt][2 * h + 1] + __ldg(bias + col + 1));
                *reinterpret_cast<float2*>(crow + col) = o;
            }
        }
    }
}

// ---------------------------------------------------------------------------
// Gather chunk-start states
// ---------------------------------------------------------------------------
__global__ void gather_kernel(const float* __restrict__ xseq,
                              const float* __restrict__ zseq,
                              float* __restrict__ X, float* __restrict__ Z)
{
    int r = blockIdx.x;
    int b = r / CCH, c = r % CCH;
    int t0 = 5 * c;
    int tid = threadIdx.x;
    X[(size_t)r*KK + tid] = xseq[((size_t)b*TT + t0)*KK + tid];
    if (tid < MM)
        Z[(size_t)r*MM + tid] = zseq[((size_t)b*TT + t0)*MM + tid];
}

// ---------------------------------------------------------------------------
// Recurrent sub-step for all NR rows (fp32). Warp-per-row; 8 rows per block.
// ---------------------------------------------------------------------------
__global__ void __launch_bounds__(256)
step_kernel(const float* __restrict__ Wz, const float* __restrict__ Azw,
            const float* __restrict__ Azb, const float* __restrict__ Lw,
            const float* __restrict__ Rw,
            float* __restrict__ X, float* __restrict__ Z,
            float* __restrict__ zpred, int step)
{
    __shared__ float sWz[64*64];
    __shared__ float sAz[8*64];
    __shared__ float sAzb[8];
    __shared__ float sL[256*8];
    __shared__ float sR[256*8];
    __shared__ float stz[8][64];
    __shared__ float stx[8][256];
    __shared__ float su[8][8];

    const int tid = threadIdx.x;
    for (int i = tid; i < 64*64; i += 256) sWz[i] = Wz[i];
    for (int i = tid; i < 8*64;  i += 256) sAz[i] = Azw[i];
    if (tid < 8) sAzb[tid] = Azb[tid];
    for (int i = tid; i < 256*8; i += 256) { sL[i] = Lw[i]; sR[i] = Rw[i]; }
    __syncthreads();

    const int w = tid / 32, lane = tid % 32;
    const int r = blockIdx.x * 8 + w;
    const int b = r / CCH, c = r % CCH;
    const int t = 5*c + step;

    float zv[2], xv[8];
    #pragma unroll
    for (int k = 0; k < 2; k++) zv[k] = Z[(size_t)r*MM + lane + 32*k];
    #pragma unroll
    for (int k = 0; k < 8; k++) xv[k] = X[(size_t)r*KK + lane + 32*k];

    #pragma unroll
    for (int k = 0; k < 2; k++) stz[w][lane + 32*k] = tanhf(zv[k]);
    #pragma unroll
    for (int k = 0; k < 8; k++) stx[w][lane + 32*k] = tanhf(xv[k]);
    __syncwarp();

    float znew[2];
    #pragma unroll
    for (int k = 0; k < 2; k++) {
        int j = lane + 32*k;
        float acc = 0.f;
        #pragma unroll 8
        for (int i = 0; i < 64; i++) acc = fmaf(stz[w][i], sWz[j*64 + i], acc);
        znew[k] = zv[k] + (acc - zv[k]) * 0.01f;
    }
    __syncwarp();
    #pragma unroll
    for (int k = 0; k < 2; k++) stz[w][lane + 32*k] = znew[k];
    __syncwarp();

    if (lane < 8) {
        float ga = 0.f;
        #pragma unroll 8
        for (int i = 0; i < 64; i++) ga = fmaf(stz[w][i], sAz[lane*64 + i], ga);
        float sg = 1.f / (1.f + expf(-(ga + sAzb[lane])));
        float ua = 0.f;
        #pragma unroll 8
        for (int i = 0; i < 256; i++) ua = fmaf(stx[w][i], sL[i*8 + lane], ua);
        su[w][lane] = ua * sg;
    }
    __syncwarp();

    float uu[8];
    #pragma unroll
    for (int i = 0; i < 8; i++) uu[i] = su[w][i];

    #pragma unroll
    for (int k = 0; k < 8; k++) {
        int j = lane + 32*k;
        float acc = 0.f;
        #pragma unroll
        for (int i = 0; i < 8; i++) acc = fmaf(uu[i], sR[j*8 + i], acc);
        X[(size_t)r*KK + j] = xv[k] + (acc - xv[k]) * 0.01f;
    }

    #pragma unroll
    for (int k = 0; k < 2; k++) {
        Z[(size_t)r*MM + lane + 32*k] = znew[k];
        if (t < TT)
            zpred[((size_t)b*TT + t)*MM + lane + 32*k] = znew[k];
    }
}

// ---------------------------------------------------------------------------
extern "C" void kernel_launch(void* const* d_in, const int* in_sizes, int n_in,
                              void* d_out, int out_size)
{
    (void)in_sizes; (void)n_in; (void)out_size;
    const float* in_seq = (const float*)d_in[0];
    const float* L      = (const float*)d_in[1];
    const float* Rm     = (const float*)d_in[2];
    const float* Wz     = (const float*)d_in[3];
    const float* Az_w   = (const float*)d_in[4];
    const float* Az_b   = (const float*)d_in[5];
    const float* ex1_w  = (const float*)d_in[6];
    const float* ex1_b  = (const float*)d_in[7];
    const float* ex2_w  = (const float*)d_in[8];
    const float* ex2_b  = (const float*)d_in[9];
    const float* ex3_w  = (const float*)d_in[10];
    const float* ex3_b  = (const float*)d_in[11];
    const float* ez1_w  = (const float*)d_in[12];
    const float* ez1_b  = (const float*)d_in[13];
    const float* ez2_w  = (const float*)d_in[14];
    const float* ez2_b  = (const float*)d_in[15];
    const float* ez3_w  = (const float*)d_in[16];
    const float* ez3_b  = (const float*)d_in[17];
    const float* de1_w  = (const float*)d_in[18];
    const float* de1_b  = (const float*)d_in[19];
    const float* de2_w  = (const float*)d_in[20];
    const float* de2_b  = (const float*)d_in[21];

    float* out    = (float*)d_out;
    float* x_pred = out;
    float* x_rec  = out + (size_t)BB*TT*PP;
    float* z_pred = out + 2*(size_t)BB*TT*PP;
    float* z_seq  = z_pred + (size_t)BB*TT*MM;

    float *bufA, *bufB, *xseq, *Xs, *Zs, *Hs;
    cudaGetSymbolAddress((void**)&bufA, g_bufA);
    cudaGetSymbolAddress((void**)&bufB, g_bufB);
    cudaGetSymbolAddress((void**)&xseq, g_xseq);
    cudaGetSymbolAddress((void**)&Xs,   g_X);
    cudaGetSymbolAddress((void**)&Zs,   g_Z);
    cudaGetSymbolAddress((void**)&Hs,   g_Hs);

    #define HGEMM(BNV, A, W, Bv, C, Mv, Nv, Kdv, ldcv, modev, stepv)           \
        gemm_hmma<BNV><<<dim3((Nv)/(BNV), (Mv)/128), 256>>>(A, W, Bv, C,       \
                                               Kdv, ldcv, modev, stepv)

    // Encoders
    HGEMM(128, in_seq, ex1_w, ex1_b, bufA,  NROWS, KK, PP, KK, 0, 0);
    HGEMM(128, bufA,   ex2_w, ex2_b, bufB,  NROWS, KK, KK, KK, 0, 0);
    HGEMM(128, bufB,   ex3_w, ex3_b, xseq,  NROWS, KK, KK, KK, 0, 0);
    HGEMM(64,  in_seq, ez1_w, ez1_b, bufA,  NROWS, MM, PP, MM, 0, 0);
    HGEMM(64,  bufA,   ez2_w, ez2_b, bufB,  NROWS, MM, MM, MM, 0, 0);
    HGEMM(64,  bufB,   ez3_w, ez3_b, z_seq, NROWS, MM, MM, MM, 0, 0);

    // x_recon = dec(x_seq)
    HGEMM(128, xseq, de1_w, de1_b, bufA,  NROWS, KK, KK, KK, 0, 0);
    HGEMM(128, bufA, de2_w, de2_b, x_rec, NROWS, PP, KK, PP, 0, 0);

    // Chunk-start states
    gather_kernel<<<NR, 256>>>(xseq, z_seq, Xs, Zs);

    // 5 global sub-steps over all 13120 independent rows
    for (int s = 0; s < 5; s++) {
        step_kernel<<<NR/8, 256>>>(Wz, Az_w, Az_b, L, Rm, Xs, Zs, z_pred, s);
        HGEMM(128, Xs, de1_w, de1_b, Hs,     NRP, KK, KK, KK, 0, 0);
        HGEMM(128, Hs, de2_w, de2_b, x_pred, NRP, PP, KK, PP, 1, s);
    }
    #undef HGEMM
}

// round 4
// speedup vs baseline: 3.4746x; 1.1149x over previous
#include <cuda_runtime.h>
#include <cuda_fp16.h>
#include <math.h>
#include <stdint.h>

// Problem constants
#define BB 32
#define TT 2048
#define PP 128
#define KK 256
#define MM 64
#define CCH 410            // independent 5-step chunks
#define NR (BB*CCH)        // 13120 state rows
#define NRP 13184          // NR padded to 128 multiple
#define NROWS (BB*TT)      // 65536 encoder rows

// fp16 weight pack offsets (in halfs)
#define W_EX1 0
#define W_EX2 32768
#define W_EX3 98304
#define W_EZ1 163840
#define W_EZ2 172032
#define W_EZ3 176128
#define W_DE1 180224
#define W_DE2 245760
#define W_TOTAL 278528

// Scratch (device globals; zero-initialized)
__device__ __half g_in16[NROWS*PP];
__device__ __half g_bufA16[NROWS*KK];
__device__ __half g_bufB16[NROWS*KK];
__device__ __half g_xseq16[NROWS*KK];
__device__ __half g_X16[NRP*KK];    // pad rows stay 0
__device__ __half g_Hs16[NRP*KK];
__device__ __half g_w16[W_TOTAL];
__device__ float  g_X[NRP*KK];      // fp32 scan state; pad rows stay 0
__device__ float  g_Z[NR*MM];

// ---------------------------------------------------------------------------
// helpers
// ---------------------------------------------------------------------------
__device__ __forceinline__ void cpa16(uint32_t dst, const void* src) {
    asm volatile("cp.async.cg.shared.global [%0], [%1], 16;\n"
                 :: "r"(dst), "l"(src));
}
__device__ __forceinline__ void ldsm4(uint32_t* r, uint32_t addr) {
    asm volatile("ldmatrix.sync.aligned.m8n8.x4.shared.b16 {%0,%1,%2,%3}, [%4];\n"
        : "=r"(r[0]), "=r"(r[1]), "=r"(r[2]), "=r"(r[3]) : "r"(addr));
}
__device__ __forceinline__ void mma16816(float* c, const uint32_t* a,
                                         uint32_t b0, uint32_t b1) {
    asm volatile(
      "mma.sync.aligned.m16n8k16.row.col.f32.f16.f16.f32 "
      "{%0,%1,%2,%3}, {%4,%5,%6,%7}, {%8,%9}, {%0,%1,%2,%3};\n"
      : "+f"(c[0]), "+f"(c[1]), "+f"(c[2]), "+f"(c[3])
      : "r"(a[0]), "r"(a[1]), "r"(a[2]), "r"(a[3]), "r"(b0), "r"(b1));
}

// ---------------------------------------------------------------------------
// One-time conversion: in_seq and all weights fp32 -> fp16
// ---------------------------------------------------------------------------
__global__ void conv_kernel(const float* __restrict__ in_seq,
                            const float* __restrict__ ex1, const float* __restrict__ ex2,
                            const float* __restrict__ ex3, const float* __restrict__ ez1,
                            const float* __restrict__ ez2, const float* __restrict__ ez3,
                            const float* __restrict__ de1, const float* __restrict__ de2)
{
    const int NIN4 = NROWS*PP/4;
    int i4 = blockIdx.x * blockDim.x + threadIdx.x;
    if (i4 < NIN4) {
        float4 v = reinterpret_cast<const float4*>(in_seq)[i4];
        __half2 a = __floats2half2_rn(v.x, v.y), b = __floats2half2_rn(v.z, v.w);
        uint2 u = { *reinterpret_cast<unsigned*>(&a), *reinterpret_cast<unsigned*>(&b) };
        reinterpret_cast<uint2*>(g_in16)[i4] = u;
        return;
    }
    int j = (i4 - NIN4) * 4;
    if (j >= W_TOTAL) return;
    const float* src; int off;
    if      (j < W_EX2) { src = ex1; off = W_EX1; }
    else if (j < W_EX3) { src = ex2; off = W_EX2; }
    else if (j < W_EZ1) { src = ex3; off = W_EX3; }
    else if (j < W_EZ2) { src = ez1; off = W_EZ1; }
    else if (j < W_EZ3) { src = ez2; off = W_EZ2; }
    else if (j < W_DE1) { src = ez3; off = W_EZ3; }
    else if (j < W_DE2) { src = de1; off = W_DE1; }
    else                { src = de2; off = W_DE2; }
    float4 v = reinterpret_cast<const float4*>(src)[(j - off) >> 2];
    __half2 a = __floats2half2_rn(v.x, v.y), b = __floats2half2_rn(v.z, v.w);
    uint2 u = { *reinterpret_cast<unsigned*>(&a), *reinterpret_cast<unsigned*>(&b) };
    *reinterpret_cast<uint2*>(&g_w16[j]) = u;
}

// ---------------------------------------------------------------------------
// Tensor-core GEMM, fp16 in / fp16+fp32 out: out = tanh(A @ W^T + bias)
// A: rows x Kd fp16 row-major, W: N x Kd fp16 row-major.
// Block tile 128 x BN x 32, 4-stage cp.async pipeline, 8 warps (4m x 2n).
// mode 0: dense (out16 and/or out32)
// mode 1: dense out16 + state init: rows with t%5==0 -> g_X (fp32) + g_X16
// mode 2: dense out32 + state init: rows with t%5==0 -> g_Z (fp32)
// mode 3: scatter fp32: r -> (b,c,t=5c+step) into out32, skip r>=NR / t>=T
// ---------------------------------------------------------------------------
template<int BN>
__global__ void __launch_bounds__(256)
gemm16(const __half* __restrict__ A, const __half* __restrict__ W,
       const float* __restrict__ bias,
       __half* __restrict__ out16, float* __restrict__ out32,
       int Kd, int ldc, int mode, int step)
{
    constexpr int BM = 128;
    constexpr int BK = 32;
    constexpr int NS = 4;               // pipeline stages
    constexpr int WN = BN / 2;
    constexpr int NT = WN / 8;
    constexpr int PITCH = 40;           // halfs per smem row (80 B, 16B-aligned)

    extern __shared__ __half smem[];
    __half* sA = smem;                       // NS * BM * PITCH
    __half* sB = smem + NS * BM * PITCH;     // NS * BN * PITCH

    const int tid  = threadIdx.x;
    const int lane = tid & 31;
    const int wid  = tid >> 5;
    const int wm   = wid & 3;
    const int wn   = wid >> 2;
    const int row0 = blockIdx.y * BM;
    const int col0 = blockIdx.x * BN;

    const uint32_t baseA0 = (uint32_t)__cvta_generic_to_shared(sA);
    const uint32_t baseB0 = (uint32_t)__cvta_generic_to_shared(sB);

    // staging maps
    const int arow_s = tid >> 1;            // 0..127
    const int aoff_s = (tid & 1) << 4;      // 0 or 16 halfs
    const int brow_s = (BN == 128) ? (tid >> 1) : (tid >> 2);
    const int boff_s = (BN == 128) ? ((tid & 1) << 4) : ((tid & 3) << 3);

    const __half* gA = A + (size_t)(row0 + arow_s) * Kd + aoff_s;
    const __half* gB = W + (size_t)(col0 + brow_s) * Kd + boff_s;
    const uint32_t dA = baseA0 + (uint32_t)((arow_s * PITCH + aoff_s) * 2);
    const uint32_t dB = baseB0 + (uint32_t)((brow_s * PITCH + boff_s) * 2);

    // ldmatrix lane addresses
    const int arow = wm * 32 + (lane & 15);
    const int akof = (lane >> 4) << 3;
    const int brow = wn * WN + (lane & 7) + ((lane >> 4) << 3);
    const int bkof = ((lane >> 3) & 1) << 3;

    float acc[2][NT][4];
    #pragma unroll
    for (int i = 0; i < 2; i++)
        #pragma unroll
        for (int j = 0; j < NT; j++)
            #pragma unroll
            for (int q = 0; q < 4; q++) acc[i][j][q] = 0.f;

    const int S = Kd / BK;

    auto issue = [&](int s, int slot) {
        const __half* pa = gA + s * BK;
        uint32_t da = dA + (uint32_t)(slot * BM * PITCH * 2);
        cpa16(da,      pa);
        cpa16(da + 16, pa + 8);
        const __half* pb = gB + s * BK;
        uint32_t db = dB + (uint32_t)(slot * BN * PITCH * 2);
        if (BN == 128) {
            cpa16(db,      pb);
            cpa16(db + 16, pb + 8);
        } else {
            cpa16(db, pb);
        }
    };

    #pragma unroll
    for (int i = 0; i < NS - 1; i++) {
        if (i < S) issue(i, i);
        asm volatile("cp.async.commit_group;\n" ::: "memory");
    }

    for (int s = 0; s < S; s++) {
        asm volatile("cp.async.wait_group %0;\n" :: "n"(NS - 2) : "memory");
        __syncthreads();
        int nxt = s + NS - 1;
        if (nxt < S) issue(nxt, nxt & (NS - 1));
        asm volatile("cp.async.commit_group;\n" ::: "memory");

        const int slot = s & (NS - 1);
        const uint32_t bA = baseA0 + (uint32_t)(slot * BM * PITCH * 2);
        const uint32_t bB = baseB0 + (uint32_t)(slot * BN * PITCH * 2);
        #pragma unroll
        for (int kk = 0; kk < BK; kk += 16) {
            uint32_t afrag[2][4];
            uint32_t aAddr = bA + (uint32_t)((arow * PITCH + kk + akof) * 2);
            ldsm4(afrag[0], aAddr);
            ldsm4(afrag[1], aAddr + 16 * PITCH * 2);
            #pragma unroll
            for (int j2 = 0; j2 < NT / 2; j2++) {
                uint32_t bfrag[4];
                ldsm4(bfrag, bB + (uint32_t)(((brow + j2 * 16) * PITCH + kk + bkof) * 2));
                mma16816(acc[0][2 * j2],     afrag[0], bfrag[0], bfrag[1]);
                mma16816(acc[0][2 * j2 + 1], afrag[0], bfrag[2], bfrag[3]);
                mma16816(acc[1][2 * j2],     afrag[1], bfrag[0], bfrag[1]);
                mma16816(acc[1][2 * j2 + 1], afrag[1], bfrag[2], bfrag[3]);
            }
        }
    }

    // ---- epilogue: bias + tanh + routed stores ----
    const int g  = lane >> 2;
    const int cq = (lane & 3) << 1;
    #pragma unroll
    for (int i = 0; i < 2; i++) {
        #pragma unroll
        for (int h = 0; h < 2; h++) {
            const int r = row0 + wm * 32 + i * 16 + h * 8 + g;
            // scatter target (mode 3)
            float* crow3 = nullptr;
            if (mode == 3) {
                if (r < NR) {
                    int b = r / CCH, c = r % CCH;
                    int t = 5 * c + step;
                    if (t < TT) crow3 = out32 + ((size_t)b * TT + t) * ldc;
                }
                if (!crow3) continue;
            }
            // state-init target (modes 1,2)
            int rs = -1;
            if (mode == 1 || mode == 2) {
                int t = r & (TT - 1);
                if (t % 5 == 0) rs = (r >> 11) * CCH + t / 5;
            }
            #pragma unroll
            for (int nt = 0; nt < NT; nt++) {
                const int col = col0 + wn * WN + nt * 8 + cq;
                float v0 = tanhf(acc[i][nt][2 * h + 0] + __ldg(bias + col));
                float v1 = tanhf(acc[i][nt][2 * h + 1] + __ldg(bias + col + 1));
                if (mode == 3) {
                    *reinterpret_cast<float2*>(crow3 + col) = make_float2(v0, v1);
                    continue;
                }
                if (out16) {
                    __half2 hv = __floats2half2_rn(v0, v1);
                    *reinterpret_cast<__half2*>(out16 + (size_t)r * ldc + col) = hv;
                }
                if (out32) {
                    *reinterpret_cast<float2*>(out32 + (size_t)r * ldc + col) =
                        make_float2(v0, v1);
                }
                if (rs >= 0) {
                    if (mode == 1) {
                        *reinterpret_cast<float2*>(&g_X[(size_t)rs * KK + col]) =
                            make_float2(v0, v1);
                        __half2 hv = __floats2half2_rn(v0, v1);
                        *reinterpret_cast<__half2*>(&g_X16[(size_t)rs * KK + col]) = hv;
                    } else {
                        *reinterpret_cast<float2*>(&g_Z[(size_t)rs * MM + col]) =
                            make_float2(v0, v1);
                    }
                }
            }
        }
    }
}

// ---------------------------------------------------------------------------
// Recurrent sub-step for all NR rows (fp32 state). Warp-per-row, 8 rows/block.
// ---------------------------------------------------------------------------
__global__ void __launch_bounds__(256)
step_kernel(const float* __restrict__ Wz, const float* __restrict__ Azw,
            const float* __restrict__ Azb, const float* __restrict__ Lw,
            const float* __restrict__ Rw, float* __restrict__ zpred, int step)
{
    __shared__ float sWz[64*64];
    __shared__ float sAz[8*64];
    __shared__ float sAzb[8];
    __shared__ float sL[256*8];
    __shared__ float sR[256*8];
    __shared__ float stz[8][64];
    __shared__ float stx[8][256];
    __shared__ float su[8][8];

    const int tid = threadIdx.x;
    for (int i = tid; i < 64*64; i += 256) sWz[i] = Wz[i];
    for (int i = tid; i < 8*64;  i += 256) sAz[i] = Azw[i];
    if (tid < 8) sAzb[tid] = Azb[tid];
    for (int i = tid; i < 256*8; i += 256) { sL[i] = Lw[i]; sR[i] = Rw[i]; }
    __syncthreads();

    const int w = tid / 32, lane = tid % 32;
    const int r = blockIdx.x * 8 + w;
    const int b = r / CCH, c = r % CCH;
    const int t = 5*c + step;

    float zv[2], xv[8];
    #pragma unroll
    for (int k = 0; k < 2; k++) zv[k] = g_Z[(size_t)r*MM + lane + 32*k];
    #pragma unroll
    for (int k = 0; k < 8; k++) xv[k] = g_X[(size_t)r*KK + lane + 32*k];

    #pragma unroll
    for (int k = 0; k < 2; k++) stz[w][lane + 32*k] = tanhf(zv[k]);
    #pragma unroll
    for (int k = 0; k < 8; k++) stx[w][lane + 32*k] = tanhf(xv[k]);
    __syncwarp();

    float znew[2];
    #pragma unroll
    for (int k = 0; k < 2; k++) {
        int j = lane + 32*k;
        float acc = 0.f;
        #pragma unroll 8
        for (int i = 0; i < 64; i++) acc = fmaf(stz[w][i], sWz[j*64 + i], acc);
        znew[k] = zv[k] + (acc - zv[k]) * 0.01f;
    }
    __syncwarp();
    #pragma unroll
    for (int k = 0; k < 2; k++) stz[w][lane + 32*k] = znew[k];
    __syncwarp();

    if (lane < 8) {
        float ga = 0.f;
        #pragma unroll 8
        for (int i = 0; i < 64; i++) ga = fmaf(stz[w][i], sAz[lane*64 + i], ga);
        float sg = 1.f / (1.f + expf(-(ga + sAzb[lane])));
        float ua = 0.f;
        #pragma unroll 8
        for (int i = 0; i < 256; i++) ua = fmaf(stx[w][i], sL[i*8 + lane], ua);
        su[w][lane] = ua * sg;
    }
    __syncwarp();

    float uu[8];
    #pragma unroll
    for (int i = 0; i < 8; i++) uu[i] = su[w][i];

    #pragma unroll
    for (int k = 0; k < 8; k++) {
        int j = lane + 32*k;
        float acc = 0.f;
        #pragma unroll
        for (int i = 0; i < 8; i++) acc = fmaf(uu[i], sR[j*8 + i], acc);
        float xn = xv[k] + (acc - xv[k]) * 0.01f;
        g_X[(size_t)r*KK + j]   = xn;
        g_X16[(size_t)r*KK + j] = __float2half(xn);
    }

    #pragma unroll
    for (int k = 0; k < 2; k++) {
        g_Z[(size_t)r*MM + lane + 32*k] = znew[k];
        if (t < TT)
            zpred[((size_t)b*TT + t)*MM + lane + 32*k] = znew[k];
    }
}

// ---------------------------------------------------------------------------
extern "C" void kernel_launch(void* const* d_in, const int* in_sizes, int n_in,
                              void* d_out, int out_size)
{
    (void)in_sizes; (void)n_in; (void)out_size;
    const float* in_seq = (const float*)d_in[0];
    const float* L      = (const float*)d_in[1];
    const float* Rm     = (const float*)d_in[2];
    const float* Wz     = (const float*)d_in[3];
    const float* Az_w   = (const float*)d_in[4];
    const float* Az_b   = (const float*)d_in[5];
    const float* ex1_w  = (const float*)d_in[6];
    const float* ex1_b  = (const float*)d_in[7];
    const float* ex2_w  = (const float*)d_in[8];
    const float* ex2_b  = (const float*)d_in[9];
    const float* ex3_w  = (const float*)d_in[10];
    const float* ex3_b  = (const float*)d_in[11];
    const float* ez1_w  = (const float*)d_in[12];
    const float* ez1_b  = (const float*)d_in[13];
    const float* ez2_w  = (const float*)d_in[14];
    const float* ez2_b  = (const float*)d_in[15];
    const float* ez3_w  = (const float*)d_in[16];
    const float* ez3_b  = (const float*)d_in[17];
    const float* de1_w  = (const float*)d_in[18];
    const float* de1_b  = (const float*)d_in[19];
    const float* de2_w  = (const float*)d_in[20];
    const float* de2_b  = (const float*)d_in[21];

    float* out    = (float*)d_out;
    float* x_pred = out;
    float* x_rec  = out + (size_t)BB*TT*PP;
    float* z_pred = out + 2*(size_t)BB*TT*PP;
    float* z_seq  = z_pred + (size_t)BB*TT*MM;

    __half *in16, *bufA16, *bufB16, *xseq16, *X16, *Hs16, *w16;
    cudaGetSymbolAddress((void**)&in16,   g_in16);
    cudaGetSymbolAddress((void**)&bufA16, g_bufA16);
    cudaGetSymbolAddress((void**)&bufB16, g_bufB16);
    cudaGetSymbolAddress((void**)&xseq16, g_xseq16);
    cudaGetSymbolAddress((void**)&X16,    g_X16);
    cudaGetSymbolAddress((void**)&Hs16,   g_Hs16);
    cudaGetSymbolAddress((void**)&w16,    g_w16);

    const int SM128 = 4 * (128 + 128) * 40 * 2;   // 81920 B
    const int SM64  = 4 * (128 +  64) * 40 * 2;   // 61440 B
    cudaFuncSetAttribute(gemm16<128>, cudaFuncAttributeMaxDynamicSharedMemorySize, SM128);
    cudaFuncSetAttribute(gemm16<64>,  cudaFuncAttributeMaxDynamicSharedMemorySize, SM64);

    // 1. convert in_seq + all weights to fp16
    {
        const int TOT4 = NROWS*PP/4 + W_TOTAL/4;
        conv_kernel<<<(TOT4 + 255) / 256, 256>>>(in_seq, ex1_w, ex2_w, ex3_w,
                                                 ez1_w, ez2_w, ez3_w, de1_w, de2_w);
    }

    #define G(BNV, A, Wp, Bv, O16, O32, Mv, Nv, Kdv, ldcv, modev, stepv)        \
        gemm16<BNV><<<dim3((Nv)/(BNV), (Mv)/128), 256,                          \
                      (BNV)==128 ? SM128 : SM64>>>(A, Wp, Bv, O16, O32,         \
                                                   Kdv, ldcv, modev, stepv)

    // Encoders (x chain; ex3 also seeds scan state X)
    G(128, in16,   w16+W_EX1, ex1_b, bufA16, (float*)0, NROWS, KK, PP, KK, 0, 0);
    G(128, bufA16, w16+W_EX2, ex2_b, bufB16, (float*)0, NROWS, KK, KK, KK, 0, 0);
    G(128, bufB16, w16+W_EX3, ex3_b, xseq16, (float*)0, NROWS, KK, KK, KK, 1, 0);
    // z chain; ez3 writes z_seq output + seeds Z
    G(64,  in16,   w16+W_EZ1, ez1_b, bufA16, (float*)0, NROWS, MM, PP, MM, 0, 0);
    G(64,  bufA16, w16+W_EZ2, ez2_b, bufB16, (float*)0, NROWS, MM, MM, MM, 0, 0);
    G(64,  bufB16, w16+W_EZ3, ez3_b, (__half*)0, z_seq, NROWS, MM, MM, MM, 2, 0);
    // x_recon
    G(128, xseq16, w16+W_DE1, de1_b, bufA16, (float*)0, NROWS, KK, KK, KK, 0, 0);
    G(128, bufA16, w16+W_DE2, de2_b, (__half*)0, x_rec, NROWS, PP, KK, PP, 0, 0);

    // 5 global sub-steps over all independent chunk rows
    for (int s = 0; s < 5; s++) {
        step_kernel<<<NR/8, 256>>>(Wz, Az_w, Az_b, L, Rm, z_pred, s);
        G(128, X16,  w16+W_DE1, de1_b, Hs16, (float*)0, NRP, KK, KK, KK, 0, 0);
        G(128, Hs16, w16+W_DE2, de2_b, (__half*)0, x_pred, NRP, PP, KK, PP, 3, s);
    }
    #undef G
}

// round 5
// speedup vs baseline: 4.2400x; 1.2203x over previous
#include <cuda_runtime.h>
#include <cuda_fp16.h>
#include <math.h>
#include <stdint.h>

// Problem constants
#define BB 32
#define TT 2048
#define PP 128
#define KK 256
#define MM 64
#define CCH 410            // independent 5-step chunks
#define NR (BB*CCH)        // 13120 state rows
#define NRP 13184          // NR padded to 128 multiple
#define NROWS (BB*TT)      // 65536 encoder rows

// fp16 weight pack offsets (in halfs)
#define W_EX1 0
#define W_EX2 32768
#define W_EX3 98304
#define W_EZ1 163840
#define W_EZ2 172032
#define W_EZ3 176128
#define W_DE1 180224
#define W_DE2 245760
#define W_TOTAL 278528

// Scratch (device globals; zero-initialized)
__device__ __half g_in16[NROWS*PP];
__device__ __half g_w16[W_TOTAL];
__device__ __half g_X16[NRP*KK];    // pad rows stay 0
__device__ float  g_X[NRP*KK];      // fp32 scan state; pad rows stay 0
__device__ float  g_Z[NR*MM];

// ---------------------------------------------------------------------------
// asm helpers
// ---------------------------------------------------------------------------
__device__ __forceinline__ void cpa16(uint32_t dst, const void* src) {
    asm volatile("cp.async.cg.shared.global [%0], [%1], 16;\n"
                 :: "r"(dst), "l"(src));
}
__device__ __forceinline__ void commitg() {
    asm volatile("cp.async.commit_group;\n" ::: "memory");
}
template<int N> __device__ __forceinline__ void waitg() {
    asm volatile("cp.async.wait_group %0;\n" :: "n"(N) : "memory");
}
__device__ __forceinline__ void ldsm4(uint32_t* r, uint32_t addr) {
    asm volatile("ldmatrix.sync.aligned.m8n8.x4.shared.b16 {%0,%1,%2,%3}, [%4];\n"
        : "=r"(r[0]), "=r"(r[1]), "=r"(r[2]), "=r"(r[3]) : "r"(addr));
}
__device__ __forceinline__ void mma16816(float* c, const uint32_t* a,
                                         uint32_t b0, uint32_t b1) {
    asm volatile(
      "mma.sync.aligned.m16n8k16.row.col.f32.f16.f16.f32 "
      "{%0,%1,%2,%3}, {%4,%5,%6,%7}, {%8,%9}, {%0,%1,%2,%3};\n"
      : "+f"(c[0]), "+f"(c[1]), "+f"(c[2]), "+f"(c[3])
      : "r"(a[0]), "r"(a[1]), "r"(a[2]), "r"(a[3]), "r"(b0), "r"(b1));
}

// ---------------------------------------------------------------------------
// One-time conversion: in_seq and all weights fp32 -> fp16
// ---------------------------------------------------------------------------
__global__ void conv_kernel(const float* __restrict__ in_seq,
                            const float* __restrict__ ex1, const float* __restrict__ ex2,
                            const float* __restrict__ ex3, const float* __restrict__ ez1,
                            const float* __restrict__ ez2, const float* __restrict__ ez3,
                            const float* __restrict__ de1, const float* __restrict__ de2)
{
    const int NIN4 = NROWS*PP/4;
    int i4 = blockIdx.x * blockDim.x + threadIdx.x;
    if (i4 < NIN4) {
        float4 v = reinterpret_cast<const float4*>(in_seq)[i4];
        __half2 a = __floats2half2_rn(v.x, v.y), b = __floats2half2_rn(v.z, v.w);
        uint2 u = { *reinterpret_cast<unsigned*>(&a), *reinterpret_cast<unsigned*>(&b) };
        reinterpret_cast<uint2*>(g_in16)[i4] = u;
        return;
    }
    int j = (i4 - NIN4) * 4;
    if (j >= W_TOTAL) return;
    const float* src; int off;
    if      (j < W_EX2) { src = ex1; off = W_EX1; }
    else if (j < W_EX3) { src = ex2; off = W_EX2; }
    else if (j < W_EZ1) { src = ex3; off = W_EX3; }
    else if (j < W_EZ2) { src = ez1; off = W_EZ1; }
    else if (j < W_EZ3) { src = ez2; off = W_EZ2; }
    else if (j < W_DE1) { src = ez3; off = W_EZ3; }
    else if (j < W_DE2) { src = de1; off = W_DE1; }
    else                { src = de2; off = W_DE2; }
    float4 v = reinterpret_cast<const float4*>(src)[(j - off) >> 2];
    __half2 a = __floats2half2_rn(v.x, v.y), b = __floats2half2_rn(v.z, v.w);
    uint2 u = { *reinterpret_cast<unsigned*>(&a), *reinterpret_cast<unsigned*>(&b) };
    *reinterpret_cast<uint2*>(&g_w16[j]) = u;
}

// ---------------------------------------------------------------------------
// Load a 128 x KH fp16 gmem tile into pitched smem (pitch = KH + 8)
// ---------------------------------------------------------------------------
template<int THREADS, int KH>
__device__ __forceinline__ void load_tile(const __half* __restrict__ g, __half* sDst)
{
    constexpr int AP = KH + 8;
    constexpr int CHT = 128 * KH / 8;
    const int tid = threadIdx.x;
    uint32_t d = (uint32_t)__cvta_generic_to_shared(sDst);
    #pragma unroll
    for (int c = tid; c < CHT; c += THREADS) {
        int row = c / (KH / 8), off = (c % (KH / 8)) * 8;
        cpa16(d + (uint32_t)((row * AP + off) * 2), g + (size_t)row * KH + off);
    }
    commitg(); waitg<0>(); __syncthreads();
}

// ---------------------------------------------------------------------------
// GEMM core: acc(128 x Nd) += smemA(128 x Kd, pitch Kd+8) @ gW(Nd x Kd)^T
// Weights streamed from gmem via 4-stage cp.async pipeline into sB.
// THREADS=512: 16 warps 4m x 4n; THREADS=256: 8 warps 4m x 2n.
// All shapes constexpr -> fully unrolled, immediate addressing.
// ---------------------------------------------------------------------------
template<int THREADS, int Nd, int Kd, int NT>
__device__ __forceinline__ void gemm_core(const __half* __restrict__ gW,
                                          const __half* sA, __half* sB,
                                          float (&acc)[2][NT][4])
{
    constexpr int BK = 32, NS = 4, BP = 40, AP = Kd + 8;
    constexpr int NWN = THREADS / 128;
    constexpr int WN = Nd / NWN;
    static_assert(NT == WN / 8, "NT mismatch");
    constexpr int S = Kd / BK;
    constexpr int CH = Nd * BK / 8;

    const int tid = threadIdx.x, lane = tid & 31, wid = tid >> 5;
    const int wm = wid & 3, wn = wid >> 2;
    const uint32_t aBase = (uint32_t)__cvta_generic_to_shared(sA);
    const uint32_t bBase = (uint32_t)__cvta_generic_to_shared(sB);
    const int arow = wm * 32 + (lane & 15);
    const int akof = (lane >> 4) << 3;
    const int brow = wn * WN + (lane & 7) + ((lane >> 4) << 3);
    const int bkof = ((lane >> 3) & 1) << 3;

    #pragma unroll
    for (int i = 0; i < 2; i++)
        #pragma unroll
        for (int j = 0; j < NT; j++)
            #pragma unroll
            for (int q = 0; q < 4; q++) acc[i][j][q] = 0.f;

    auto issueB = [&](int s, int slot) {
        #pragma unroll
        for (int c = tid; c < CH; c += THREADS) {
            int row = c >> 2, off = (c & 3) << 3;
            cpa16(bBase + (uint32_t)(((slot * Nd + row) * BP + off) * 2),
                  gW + (size_t)row * Kd + s * BK + off);
        }
    };

    #pragma unroll
    for (int i = 0; i < NS - 1; i++) { if (i < S) issueB(i, i); commitg(); }

    #pragma unroll
    for (int s = 0; s < S; s++) {
        waitg<NS - 2>();
        __syncthreads();
        if (s + NS - 1 < S) issueB(s + NS - 1, (s + NS - 1) & (NS - 1));
        commitg();
        const int slot = s & (NS - 1);
        #pragma unroll
        for (int kk = 0; kk < BK; kk += 16) {
            uint32_t af[2][4];
            uint32_t aa = aBase + (uint32_t)((arow * AP + s * BK + kk + akof) * 2);
            ldsm4(af[0], aa);
            ldsm4(af[1], aa + 16 * AP * 2);
            #pragma unroll
            for (int j2 = 0; j2 < NT / 2; j2++) {
                uint32_t bf[4];
                ldsm4(bf, bBase + (uint32_t)(((slot * Nd + brow + j2 * 16) * BP + kk + bkof) * 2));
                mma16816(acc[0][2 * j2],     af[0], bf[0], bf[1]);
                mma16816(acc[0][2 * j2 + 1], af[0], bf[2], bf[3]);
                mma16816(acc[1][2 * j2],     af[1], bf[0], bf[1]);
                mma16816(acc[1][2 * j2 + 1], af[1], bf[2], bf[3]);
            }
        }
    }
}

// ---------------------------------------------------------------------------
// Epilogue: tanh(acc + bias) -> pitched smem (pitch Nd + 8)
// ---------------------------------------------------------------------------
template<int THREADS, int Nd, int NT>
__device__ __forceinline__ void epi_to_smem(float (&acc)[2][NT][4],
        const float* __restrict__ bias, __half* sOut)
{
    constexpr int NWN = THREADS / 128, WN = Nd / NWN, OP = Nd + 8;
    const int tid = threadIdx.x, lane = tid & 31, wid = tid >> 5;
    const int wm = wid & 3, wn = wid >> 2;
    const int g = lane >> 2, cq = (lane & 3) << 1;
    #pragma unroll
    for (int i = 0; i < 2; i++)
        #pragma unroll
        for (int h = 0; h < 2; h++) {
            const int row = wm * 32 + i * 16 + h * 8 + g;
            #pragma unroll
            for (int nt = 0; nt < NT; nt++) {
                const int col = wn * WN + nt * 8 + cq;
                float v0 = tanhf(acc[i][nt][2 * h + 0] + __ldg(bias + col));
                float v1 = tanhf(acc[i][nt][2 * h + 1] + __ldg(bias + col + 1));
                *reinterpret_cast<__half2*>(sOut + row * OP + col) =
                    __floats2half2_rn(v0, v1);
            }
        }
}

// ---------------------------------------------------------------------------
// fused_x: per 128-row tile: in16 -> ex1 -> ex2 -> ex3 (state init)
//          -> de1 -> de2 -> x_rec (fp32)
// smem: sA0[128*264], sA1[128*264], sB[4*256*40]  = 217088 B
// ---------------------------------------------------------------------------
__global__ void __launch_bounds__(512, 1)
fused_x(const float* __restrict__ bx1, const float* __restrict__ bx2,
        const float* __restrict__ bx3, const float* __restrict__ bd1,
        const float* __restrict__ bd2, float* __restrict__ x_rec)
{
    extern __shared__ __half sm[];
    __half* sA0 = sm;
    __half* sA1 = sm + 33792;
    __half* sB  = sm + 67584;
    const int row0 = blockIdx.x * 128;
    const int tid = threadIdx.x, lane = tid & 31, wid = tid >> 5;
    const int wm = wid & 3, wn = wid >> 2;
    const int g = lane >> 2, cq = (lane & 3) << 1;

    load_tile<512, 128>(g_in16 + (size_t)row0 * PP, sA0);

    {   float acc[2][8][4];
        gemm_core<512, 256, 128, 8>(g_w16 + W_EX1, sA0, sB, acc);
        epi_to_smem<512, 256, 8>(acc, bx1, sA1);
    }
    __syncthreads();
    {   float acc[2][8][4];
        gemm_core<512, 256, 256, 8>(g_w16 + W_EX2, sA1, sB, acc);
        epi_to_smem<512, 256, 8>(acc, bx2, sA0);
    }
    __syncthreads();
    {   // ex3: activation to sA1 + scan-state init
        float acc[2][8][4];
        gemm_core<512, 256, 256, 8>(g_w16 + W_EX3, sA0, sB, acc);
        #pragma unroll
        for (int i = 0; i < 2; i++)
            #pragma unroll
            for (int h = 0; h < 2; h++) {
                const int row = wm * 32 + i * 16 + h * 8 + g;
                const int r = row0 + row;
                const int t = r & (TT - 1);
                const int rs = (t % 5 == 0) ? ((r >> 11) * CCH + t / 5) : -1;
                #pragma unroll
                for (int nt = 0; nt < 8; nt++) {
                    const int col = wn * 64 + nt * 8 + cq;
                    float v0 = tanhf(acc[i][nt][2 * h + 0] + __ldg(bx3 + col));
                    float v1 = tanhf(acc[i][nt][2 * h + 1] + __ldg(bx3 + col + 1));
                    __half2 hv = __floats2half2_rn(v0, v1);
                    *reinterpret_cast<__half2*>(sA1 + row * 264 + col) = hv;
                    if (rs >= 0) {
                        *reinterpret_cast<float2*>(&g_X[(size_t)rs * KK + col]) =
                            make_float2(v0, v1);
                        *reinterpret_cast<__half2*>(&g_X16[(size_t)rs * KK + col]) = hv;
                    }
                }
            }
    }
    __syncthreads();
    {   float acc[2][8][4];
        gemm_core<512, 256, 256, 8>(g_w16 + W_DE1, sA1, sB, acc);
        epi_to_smem<512, 256, 8>(acc, bd1, sA0);
    }
    __syncthreads();
    {   // de2 -> x_rec (fp32 dense)
        float acc[2][4][4];
        gemm_core<512, 128, 256, 4>(g_w16 + W_DE2, sA0, sB, acc);
        #pragma unroll
        for (int i = 0; i < 2; i++)
            #pragma unroll
            for (int h = 0; h < 2; h++) {
                const int row = wm * 32 + i * 16 + h * 8 + g;
                const int r = row0 + row;
                #pragma unroll
                for (int nt = 0; nt < 4; nt++) {
                    const int col = wn * 32 + nt * 8 + cq;
                    float v0 = tanhf(acc[i][nt][2 * h + 0] + __ldg(bd2 + col));
                    float v1 = tanhf(acc[i][nt][2 * h + 1] + __ldg(bd2 + col + 1));
                    *reinterpret_cast<float2*>(x_rec + (size_t)r * PP + col) =
                        make_float2(v0, v1);
                }
            }
    }
}

// ---------------------------------------------------------------------------
// fused_z: in16 -> ez1 -> ez2 -> ez3 -> z_seq (fp32) + Z init
// smem: sA0[128*136], sA1[128*72], sB[4*64*40] = 73728 B. 256 threads.
// ---------------------------------------------------------------------------
__global__ void __launch_bounds__(256)
fused_z(const float* __restrict__ bz1, const float* __restrict__ bz2,
        const float* __restrict__ bz3, float* __restrict__ z_seq)
{
    extern __shared__ __half sm[];
    __half* sA0 = sm;               // 17408 halfs (pitch 136); reused pitch 72
    __half* sA1 = sm + 17408;       // 9216 halfs (pitch 72)
    __half* sB  = sm + 26624;       // 10240 halfs
    const int row0 = blockIdx.x * 128;
    const int tid = threadIdx.x, lane = tid & 31, wid = tid >> 5;
    const int wm = wid & 3, wn = wid >> 2;
    const int g = lane >> 2, cq = (lane & 3) << 1;

    load_tile<256, 128>(g_in16 + (size_t)row0 * PP, sA0);

    {   float acc[2][4][4];
        gemm_core<256, 64, 128, 4>(g_w16 + W_EZ1, sA0, sB, acc);
        epi_to_smem<256, 64, 4>(acc, bz1, sA1);
    }
    __syncthreads();
    {   float acc[2][4][4];
        gemm_core<256, 64, 64, 4>(g_w16 + W_EZ2, sA1, sB, acc);
        epi_to_smem<256, 64, 4>(acc, bz2, sA0);
    }
    __syncthreads();
    {   // ez3 -> z_seq fp32 + Z init
        float acc[2][4][4];
        gemm_core<256, 64, 64, 4>(g_w16 + W_EZ3, sA0, sB, acc);
        #pragma unroll
        for (int i = 0; i < 2; i++)
            #pragma unroll
            for (int h = 0; h < 2; h++) {
                const int row = wm * 32 + i * 16 + h * 8 + g;
                const int r = row0 + row;
                const int t = r & (TT - 1);
                const int rs = (t % 5 == 0) ? ((r >> 11) * CCH + t / 5) : -1;
                #pragma unroll
                for (int nt = 0; nt < 4; nt++) {
                    const int col = wn * 32 + nt * 8 + cq;
                    float v0 = tanhf(acc[i][nt][2 * h + 0] + __ldg(bz3 + col));
                    float v1 = tanhf(acc[i][nt][2 * h + 1] + __ldg(bz3 + col + 1));
                    *reinterpret_cast<float2*>(z_seq + (size_t)r * MM + col) =
                        make_float2(v0, v1);
                    if (rs >= 0)
                        *reinterpret_cast<float2*>(&g_Z[(size_t)rs * MM + col]) =
                            make_float2(v0, v1);
                }
            }
    }
}

// ---------------------------------------------------------------------------
// fused_dec: per 128 scan-state rows: X16 -> de1 -> de2 -> scatter x_pred
// ---------------------------------------------------------------------------
__global__ void __launch_bounds__(512, 1)
fused_dec(const float* __restrict__ bd1, const float* __restrict__ bd2,
          float* __restrict__ x_pred, int step)
{
    extern __shared__ __half sm[];
    __half* sA0 = sm;
    __half* sA1 = sm + 33792;
    __half* sB  = sm + 67584;
    const int row0 = blockIdx.x * 128;
    const int tid = threadIdx.x, lane = tid & 31, wid = tid >> 5;
    const int wm = wid & 3, wn = wid >> 2;
    const int g = lane >> 2, cq = (lane & 3) << 1;

    load_tile<512, 256>(g_X16 + (size_t)row0 * KK, sA0);

    {   float acc[2][8][4];
        gemm_core<512, 256, 256, 8>(g_w16 + W_DE1, sA0, sB, acc);
        epi_to_smem<512, 256, 8>(acc, bd1, sA1);
    }
    __syncthreads();
    {   float acc[2][4][4];
        gemm_core<512, 128, 256, 4>(g_w16 + W_DE2, sA1, sB, acc);
        #pragma unroll
        for (int i = 0; i < 2; i++)
            #pragma unroll
            for (int h = 0; h < 2; h++) {
                const int row = wm * 32 + i * 16 + h * 8 + g;
                const int r = row0 + row;
                if (r >= NR) continue;
                const int b = r / CCH, c = r % CCH;
                const int t = 5 * c + step;
                if (t >= TT) continue;
                float* crow = x_pred + ((size_t)b * TT + t) * PP;
                #pragma unroll
                for (int nt = 0; nt < 4; nt++) {
                    const int col = wn * 32 + nt * 8 + cq;
                    float v0 = tanhf(acc[i][nt][2 * h + 0] + __ldg(bd2 + col));
                    float v1 = tanhf(acc[i][nt][2 * h + 1] + __ldg(bd2 + col + 1));
                    *reinterpret_cast<float2*>(crow + col) = make_float2(v0, v1);
                }
            }
    }
}

// ---------------------------------------------------------------------------
// Recurrent sub-step for all NR rows (fp32 state). Warp-per-row, 8 rows/block.
// ---------------------------------------------------------------------------
__global__ void __launch_bounds__(256)
step_kernel(const float* __restrict__ Wz, const float* __restrict__ Azw,
            const float* __restrict__ Azb, const float* __restrict__ Lw,
            const float* __restrict__ Rw, float* __restrict__ zpred, int step)
{
    __shared__ float sWz[64*64];
    __shared__ float sAz[8*64];
    __shared__ float sAzb[8];
    __shared__ float sL[256*8];
    __shared__ float sR[256*8];
    __shared__ float stz[8][64];
    __shared__ float stx[8][256];
    __shared__ float su[8][8];

    const int tid = threadIdx.x;
    for (int i = tid; i < 64*64; i += 256) sWz[i] = Wz[i];
    for (int i = tid; i < 8*64;  i += 256) sAz[i] = Azw[i];
    if (tid < 8) sAzb[tid] = Azb[tid];
    for (int i = tid; i < 256*8; i += 256) { sL[i] = Lw[i]; sR[i] = Rw[i]; }
    __syncthreads();

    const int w = tid / 32, lane = tid % 32;
    const int r = blockIdx.x * 8 + w;
    const int b = r / CCH, c = r % CCH;
    const int t = 5*c + step;

    float zv[2], xv[8];
    #pragma unroll
    for (int k = 0; k < 2; k++) zv[k] = g_Z[(size_t)r*MM + lane + 32*k];
    #pragma unroll
    for (int k = 0; k < 8; k++) xv[k] = g_X[(size_t)r*KK + lane + 32*k];

    #pragma unroll
    for (int k = 0; k < 2; k++) stz[w][lane + 32*k] = tanhf(zv[k]);
    #pragma unroll
    for (int k = 0; k < 8; k++) stx[w][lane + 32*k] = tanhf(xv[k]);
    __syncwarp();

    float znew[2];
    #pragma unroll
    for (int k = 0; k < 2; k++) {
        int j = lane + 32*k;
        float acc = 0.f;
        #pragma unroll 8
        for (int i = 0; i < 64; i++) acc = fmaf(stz[w][i], sWz[j*64 + i], acc);
        znew[k] = zv[k] + (acc - zv[k]) * 0.01f;
    }
    __syncwarp();
    #pragma unroll
    for (int k = 0; k < 2; k++) stz[w][lane + 32*k] = znew[k];
    __syncwarp();

    if (lane < 8) {
        float ga = 0.f;
        #pragma unroll 8
        for (int i = 0; i < 64; i++) ga = fmaf(stz[w][i], sAz[lane*64 + i], ga);
        float sg = 1.f / (1.f + expf(-(ga + sAzb[lane])));
        float ua = 0.f;
        #pragma unroll 8
        for (int i = 0; i < 256; i++) ua = fmaf(stx[w][i], sL[i*8 + lane], ua);
        su[w][lane] = ua * sg;
    }
    __syncwarp();

    float uu[8];
    #pragma unroll
    for (int i = 0; i < 8; i++) uu[i] = su[w][i];

    #pragma unroll
    for (int k = 0; k < 8; k++) {
        int j = lane + 32*k;
        float acc = 0.f;
        #pragma unroll
        for (int i = 0; i < 8; i++) acc = fmaf(uu[i], sR[j*8 + i], acc);
        float xn = xv[k] + (acc - xv[k]) * 0.01f;
        g_X[(size_t)r*KK + j]   = xn;
        g_X16[(size_t)r*KK + j] = __float2half(xn);
    }

    #pragma unroll
    for (int k = 0; k < 2; k++) {
        g_Z[(size_t)r*MM + lane + 32*k] = znew[k];
        if (t < TT)
            zpred[((size_t)b*TT + t)*MM + lane + 32*k] = znew[k];
    }
}

// ---------------------------------------------------------------------------
extern "C" void kernel_launch(void* const* d_in, const int* in_sizes, int n_in,
                              void* d_out, int out_size)
{
    (void)in_sizes; (void)n_in; (void)out_size;
    const float* in_seq = (const float*)d_in[0];
    const float* L      = (const float*)d_in[1];
    const float* Rm     = (const float*)d_in[2];
    const float* Wz     = (const float*)d_in[3];
    const float* Az_w   = (const float*)d_in[4];
    const float* Az_b   = (const float*)d_in[5];
    const float* ex1_w  = (const float*)d_in[6];
    const float* ex1_b  = (const float*)d_in[7];
    const float* ex2_w  = (const float*)d_in[8];
    const float* ex2_b  = (const float*)d_in[9];
    const float* ex3_w  = (const float*)d_in[10];
    const float* ex3_b  = (const float*)d_in[11];
    const float* ez1_w  = (const float*)d_in[12];
    const float* ez1_b  = (const float*)d_in[13];
    const float* ez2_w  = (const float*)d_in[14];
    const float* ez2_b  = (const float*)d_in[15];
    const float* ez3_w  = (const float*)d_in[16];
    const float* ez3_b  = (const float*)d_in[17];
    const float* de1_w  = (const float*)d_in[18];
    const float* de1_b  = (const float*)d_in[19];
    const float* de2_w  = (const float*)d_in[20];
    const float* de2_b  = (const float*)d_in[21];

    float* out    = (float*)d_out;
    float* x_pred = out;
    float* x_rec  = out + (size_t)BB*TT*PP;
    float* z_pred = out + 2*(size_t)BB*TT*PP;
    float* z_seq  = z_pred + (size_t)BB*TT*MM;

    const int SMX = (2 * 128 * 264 + 4 * 256 * 40) * 2;   // 217088 B
    const int SMZ = (128 * 136 + 128 * 72 + 4 * 64 * 40) * 2;  // 73728 B
    cudaFuncSetAttribute(fused_x,   cudaFuncAttributeMaxDynamicSharedMemorySize, SMX);
    cudaFuncSetAttribute(fused_dec, cudaFuncAttributeMaxDynamicSharedMemorySize, SMX);
    cudaFuncSetAttribute(fused_z,   cudaFuncAttributeMaxDynamicSharedMemorySize, SMZ);

    // 1. fp16 conversion of in_seq + all weights
    {
        const int TOT4 = NROWS*PP/4 + W_TOTAL/4;
        conv_kernel<<<(TOT4 + 255) / 256, 256>>>(in_seq, ex1_w, ex2_w, ex3_w,
                                                 ez1_w, ez2_w, ez3_w, de1_w, de2_w);
    }

    // 2. fused encoder->decoder chains
    fused_x<<<NROWS/128, 512, SMX>>>(ex1_b, ex2_b, ex3_b, de1_b, de2_b, x_rec);
    fused_z<<<NROWS/128, 256, SMZ>>>(ez1_b, ez2_b, ez3_b, z_seq);

    // 3. 5 global scan sub-steps
    for (int s = 0; s < 5; s++) {
        step_kernel<<<NR/8, 256>>>(Wz, Az_w, Az_b, L, Rm, z_pred, s);
        fused_dec<<<NRP/128, 512, SMX>>>(de1_b, de2_b, x_pred, s);
    }
}

// round 6
// speedup vs baseline: 8.1817x; 1.9297x over previous
#include <cuda_runtime.h>
#include <cuda_fp16.h>
#include <math.h>
#include <stdint.h>

// Problem constants
#define BB 32
#define TT 2048
#define PP 128
#define KK 256
#define MM 64
#define CCH 410            // independent 5-step chunks
#define NR (BB*CCH)        // 13120 state rows
#define NRP 13184          // NR padded to 128 multiple
#define NROWS (BB*TT)      // 65536 encoder rows

// fp16 weight pack offsets (in halfs)
#define W_EX1 0
#define W_EX2 32768
#define W_EX3 98304
#define W_EZ1 163840
#define W_EZ2 172032
#define W_EZ3 176128
#define W_DE1 180224
#define W_DE2 245760
#define W_TOTAL 278528

// fp32 step-weight pack offsets (floats)
#define P_WZT 0        // 64x64 transposed:  [i*64+j] = Wz[j*64+i]
#define P_AZT 4096     // 64x8  transposed:  [i*8+r]  = Az[r*64+i]
#define P_L   4608     // 256x12 (pitch 12, cols 0..7 = L row)
#define P_RT  7680     // 8x256 transposed:  [r*256+j] = Rm[j*8+r]
#define P_AZB 9728     // 8
#define P_TOT 9736

// Scratch (device globals; zero-initialized)
__device__ __half g_in16[NROWS*PP];
__device__ __half g_w16[W_TOTAL];
__device__ float  g_step[P_TOT];
__device__ float  g_X[NRP*KK];                  // fp32 scan-state init; pad rows 0
__device__ float  g_Z[NR*MM];
__device__ __half g_X16s[(size_t)5*NRP*KK];     // per-step x snapshots; pad rows 0

// ---------------------------------------------------------------------------
// asm helpers
// ---------------------------------------------------------------------------
__device__ __forceinline__ void cpa16(uint32_t dst, const void* src) {
    asm volatile("cp.async.cg.shared.global [%0], [%1], 16;\n"
                 :: "r"(dst), "l"(src));
}
__device__ __forceinline__ void commitg() {
    asm volatile("cp.async.commit_group;\n" ::: "memory");
}
template<int N> __device__ __forceinline__ void waitg() {
    asm volatile("cp.async.wait_group %0;\n" :: "n"(N) : "memory");
}
__device__ __forceinline__ void ldsm4(uint32_t* r, uint32_t addr) {
    asm volatile("ldmatrix.sync.aligned.m8n8.x4.shared.b16 {%0,%1,%2,%3}, [%4];\n"
        : "=r"(r[0]), "=r"(r[1]), "=r"(r[2]), "=r"(r[3]) : "r"(addr));
}
__device__ __forceinline__ void mma16816(float* c, const uint32_t* a,
                                         uint32_t b0, uint32_t b1) {
    asm volatile(
      "mma.sync.aligned.m16n8k16.row.col.f32.f16.f16.f32 "
      "{%0,%1,%2,%3}, {%4,%5,%6,%7}, {%8,%9}, {%0,%1,%2,%3};\n"
      : "+f"(c[0]), "+f"(c[1]), "+f"(c[2]), "+f"(c[3])
      : "r"(a[0]), "r"(a[1]), "r"(a[2]), "r"(a[3]), "r"(b0), "r"(b1));
}

// ---------------------------------------------------------------------------
// One-time conversion: in_seq + weights -> fp16; step weights -> transposed pack
// ---------------------------------------------------------------------------
__global__ void conv_kernel(const float* __restrict__ in_seq,
                            const float* __restrict__ ex1, const float* __restrict__ ex2,
                            const float* __restrict__ ex3, const float* __restrict__ ez1,
                            const float* __restrict__ ez2, const float* __restrict__ ez3,
                            const float* __restrict__ de1, const float* __restrict__ de2,
                            const float* __restrict__ Wz,  const float* __restrict__ Azw,
                            const float* __restrict__ Azb, const float* __restrict__ Lw,
                            const float* __restrict__ Rm)
{
    const int NIN4 = NROWS*PP/4;
    int i4 = blockIdx.x * blockDim.x + threadIdx.x;
    if (i4 < NIN4) {
        float4 v = reinterpret_cast<const float4*>(in_seq)[i4];
        __half2 a = __floats2half2_rn(v.x, v.y), b = __floats2half2_rn(v.z, v.w);
        uint2 u = { *reinterpret_cast<unsigned*>(&a), *reinterpret_cast<unsigned*>(&b) };
        reinterpret_cast<uint2*>(g_in16)[i4] = u;
        return;
    }
    int j = (i4 - NIN4) * 4;
    if (j < W_TOTAL) {
        const float* src; int off;
        if      (j < W_EX2) { src = ex1; off = W_EX1; }
        else if (j < W_EX3) { src = ex2; off = W_EX2; }
        else if (j < W_EZ1) { src = ex3; off = W_EX3; }
        else if (j < W_EZ2) { src = ez1; off = W_EZ1; }
        else if (j < W_EZ3) { src = ez2; off = W_EZ2; }
        else if (j < W_DE1) { src = ez3; off = W_EZ3; }
        else if (j < W_DE2) { src = de1; off = W_DE1; }
        else                { src = de2; off = W_DE2; }
        float4 v = reinterpret_cast<const float4*>(src)[(j - off) >> 2];
        __half2 a = __floats2half2_rn(v.x, v.y), b = __floats2half2_rn(v.z, v.w);
        uint2 u = { *reinterpret_cast<unsigned*>(&a), *reinterpret_cast<unsigned*>(&b) };
        *reinterpret_cast<uint2*>(&g_w16[j]) = u;
        return;
    }
    int sidx = i4 - NIN4 - W_TOTAL/4;
    if (sidx >= P_TOT) return;
    float v;
    if (sidx < P_AZT) {
        v = Wz[(sidx & 63)*64 + (sidx >> 6)];
    } else if (sidx < P_L) {
        int q = sidx - P_AZT;
        v = Azw[(q & 7)*64 + (q >> 3)];
    } else if (sidx < P_RT) {
        int q = sidx - P_L;
        int row = q / 12, col = q % 12;
        v = (col < 8) ? Lw[row*8 + col] : 0.f;
    } else if (sidx < P_AZB) {
        int q = sidx - P_RT;
        v = Rm[(q & 255)*8 + (q >> 8)];
    } else {
        v = Azb[sidx - P_AZB];
    }
    g_step[sidx] = v;
}

// ---------------------------------------------------------------------------
// Load a 128 x KH fp16 gmem tile into pitched smem (pitch = KH + 8)
// ---------------------------------------------------------------------------
template<int THREADS, int KH>
__device__ __forceinline__ void load_tile(const __half* __restrict__ g, __half* sDst)
{
    constexpr int AP = KH + 8;
    constexpr int CHT = 128 * KH / 8;
    const int tid = threadIdx.x;
    uint32_t d = (uint32_t)__cvta_generic_to_shared(sDst);
    #pragma unroll
    for (int c = tid; c < CHT; c += THREADS) {
        int row = c / (KH / 8), off = (c % (KH / 8)) * 8;
        cpa16(d + (uint32_t)((row * AP + off) * 2), g + (size_t)row * KH + off);
    }
    commitg(); waitg<0>(); __syncthreads();
}

// ---------------------------------------------------------------------------
// GEMM core: acc(128 x Nd) += smemA(128 x Kd, pitch Kd+8) @ gW(Nd x Kd)^T
// ---------------------------------------------------------------------------
template<int THREADS, int Nd, int Kd, int NT>
__device__ __forceinline__ void gemm_core(const __half* __restrict__ gW,
                                          const __half* sA, __half* sB,
                                          float (&acc)[2][NT][4])
{
    constexpr int BK = 32, NS = 4, BP = 40, AP = Kd + 8;
    constexpr int NWN = THREADS / 128;
    constexpr int WN = Nd / NWN;
    static_assert(NT == WN / 8, "NT mismatch");
    constexpr int S = Kd / BK;
    constexpr int CH = Nd * BK / 8;

    const int tid = threadIdx.x, lane = tid & 31, wid = tid >> 5;
    const int wm = wid & 3, wn = wid >> 2;
    const uint32_t aBase = (uint32_t)__cvta_generic_to_shared(sA);
    const uint32_t bBase = (uint32_t)__cvta_generic_to_shared(sB);
    const int arow = wm * 32 + (lane & 15);
    const int akof = (lane >> 4) << 3;
    const int brow = wn * WN + (lane & 7) + ((lane >> 4) << 3);
    const int bkof = ((lane >> 3) & 1) << 3;

    #pragma unroll
    for (int i = 0; i < 2; i++)
        #pragma unroll
        for (int j = 0; j < NT; j++)
            #pragma unroll
            for (int q = 0; q < 4; q++) acc[i][j][q] = 0.f;

    auto issueB = [&](int s, int slot) {
        #pragma unroll
        for (int c = tid; c < CH; c += THREADS) {
            int row = c >> 2, off = (c & 3) << 3;
            cpa16(bBase + (uint32_t)(((slot * Nd + row) * BP + off) * 2),
                  gW + (size_t)row * Kd + s * BK + off);
        }
    };

    #pragma unroll
    for (int i = 0; i < NS - 1; i++) { if (i < S) issueB(i, i); commitg(); }

    #pragma unroll
    for (int s = 0; s < S; s++) {
        waitg<NS - 2>();
        __syncthreads();
        if (s + NS - 1 < S) issueB(s + NS - 1, (s + NS - 1) & (NS - 1));
        commitg();
        const int slot = s & (NS - 1);
        #pragma unroll
        for (int kk = 0; kk < BK; kk += 16) {
            uint32_t af[2][4];
            uint32_t aa = aBase + (uint32_t)((arow * AP + s * BK + kk + akof) * 2);
            ldsm4(af[0], aa);
            ldsm4(af[1], aa + 16 * AP * 2);
            #pragma unroll
            for (int j2 = 0; j2 < NT / 2; j2++) {
                uint32_t bf[4];
                ldsm4(bf, bBase + (uint32_t)(((slot * Nd + brow + j2 * 16) * BP + kk + bkof) * 2));
                mma16816(acc[0][2 * j2],     af[0], bf[0], bf[1]);
                mma16816(acc[0][2 * j2 + 1], af[0], bf[2], bf[3]);
                mma16816(acc[1][2 * j2],     af[1], bf[0], bf[1]);
                mma16816(acc[1][2 * j2 + 1], af[1], bf[2], bf[3]);
            }
        }
    }
}

// ---------------------------------------------------------------------------
// Epilogue: tanh(acc + bias) -> pitched smem (pitch Nd + 8)
// ---------------------------------------------------------------------------
template<int THREADS, int Nd, int NT>
__device__ __forceinline__ void epi_to_smem(float (&acc)[2][NT][4],
        const float* __restrict__ bias, __half* sOut)
{
    constexpr int NWN = THREADS / 128, WN = Nd / NWN, OP = Nd + 8;
    const int tid = threadIdx.x, lane = tid & 31, wid = tid >> 5;
    const int wm = wid & 3, wn = wid >> 2;
    const int g = lane >> 2, cq = (lane & 3) << 1;
    #pragma unroll
    for (int i = 0; i < 2; i++)
        #pragma unroll
        for (int h = 0; h < 2; h++) {
            const int row = wm * 32 + i * 16 + h * 8 + g;
            #pragma unroll
            for (int nt = 0; nt < NT; nt++) {
                const int col = wn * WN + nt * 8 + cq;
                float v0 = tanhf(acc[i][nt][2 * h + 0] + __ldg(bias + col));
                float v1 = tanhf(acc[i][nt][2 * h + 1] + __ldg(bias + col + 1));
                *reinterpret_cast<__half2*>(sOut + row * OP + col) =
                    __floats2half2_rn(v0, v1);
            }
        }
}

// ---------------------------------------------------------------------------
// fused_x: per 128-row tile: in16 -> ex1 -> ex2 -> ex3 (state init fp32)
//          -> de1 -> de2 -> x_rec (fp32)
// ---------------------------------------------------------------------------
__global__ void __launch_bounds__(512, 1)
fused_x(const float* __restrict__ bx1, const float* __restrict__ bx2,
        const float* __restrict__ bx3, const float* __restrict__ bd1,
        const float* __restrict__ bd2, float* __restrict__ x_rec)
{
    extern __shared__ __half sm[];
    __half* sA0 = sm;
    __half* sA1 = sm + 33792;
    __half* sB  = sm + 67584;
    const int row0 = blockIdx.x * 128;
    const int tid = threadIdx.x, lane = tid & 31, wid = tid >> 5;
    const int wm = wid & 3, wn = wid >> 2;
    const int g = lane >> 2, cq = (lane & 3) << 1;

    load_tile<512, 128>(g_in16 + (size_t)row0 * PP, sA0);

    {   float acc[2][8][4];
        gemm_core<512, 256, 128, 8>(g_w16 + W_EX1, sA0, sB, acc);
        epi_to_smem<512, 256, 8>(acc, bx1, sA1);
    }
    __syncthreads();
    {   float acc[2][8][4];
        gemm_core<512, 256, 256, 8>(g_w16 + W_EX2, sA1, sB, acc);
        epi_to_smem<512, 256, 8>(acc, bx2, sA0);
    }
    __syncthreads();
    {   // ex3: activation to sA1 + fp32 scan-state init
        float acc[2][8][4];
        gemm_core<512, 256, 256, 8>(g_w16 + W_EX3, sA0, sB, acc);
        #pragma unroll
        for (int i = 0; i < 2; i++)
            #pragma unroll
            for (int h = 0; h < 2; h++) {
                const int row = wm * 32 + i * 16 + h * 8 + g;
                const int r = row0 + row;
                const int t = r & (TT - 1);
                const int rs = (t % 5 == 0) ? ((r >> 11) * CCH + t / 5) : -1;
                #pragma unroll
                for (int nt = 0; nt < 8; nt++) {
                    const int col = wn * 64 + nt * 8 + cq;
                    float v0 = tanhf(acc[i][nt][2 * h + 0] + __ldg(bx3 + col));
                    float v1 = tanhf(acc[i][nt][2 * h + 1] + __ldg(bx3 + col + 1));
                    *reinterpret_cast<__half2*>(sA1 + row * 264 + col) =
                        __floats2half2_rn(v0, v1);
                    if (rs >= 0)
                        *reinterpret_cast<float2*>(&g_X[(size_t)rs * KK + col]) =
                            make_float2(v0, v1);
                }
            }
    }
    __syncthreads();
    {   float acc[2][8][4];
        gemm_core<512, 256, 256, 8>(g_w16 + W_DE1, sA1, sB, acc);
        epi_to_smem<512, 256, 8>(acc, bd1, sA0);
    }
    __syncthreads();
    {   // de2 -> x_rec (fp32 dense)
        float acc[2][4][4];
        gemm_core<512, 128, 256, 4>(g_w16 + W_DE2, sA0, sB, acc);
        #pragma unroll
        for (int i = 0; i < 2; i++)
            #pragma unroll
            for (int h = 0; h < 2; h++) {
                const int row = wm * 32 + i * 16 + h * 8 + g;
                const int r = row0 + row;
                #pragma unroll
                for (int nt = 0; nt < 4; nt++) {
                    const int col = wn * 32 + nt * 8 + cq;
                    float v0 = tanhf(acc[i][nt][2 * h + 0] + __ldg(bd2 + col));
                    float v1 = tanhf(acc[i][nt][2 * h + 1] + __ldg(bd2 + col + 1));
                    *reinterpret_cast<float2*>(x_rec + (size_t)r * PP + col) =
                        make_float2(v0, v1);
                }
            }
    }
}

// ---------------------------------------------------------------------------
// fused_z: in16 -> ez1 -> ez2 -> ez3 -> z_seq (fp32) + Z init
// ---------------------------------------------------------------------------
__global__ void __launch_bounds__(256)
fused_z(const float* __restrict__ bz1, const float* __restrict__ bz2,
        const float* __restrict__ bz3, float* __restrict__ z_seq)
{
    extern __shared__ __half sm[];
    __half* sA0 = sm;
    __half* sA1 = sm + 17408;
    __half* sB  = sm + 26624;
    const int row0 = blockIdx.x * 128;
    const int tid = threadIdx.x, lane = tid & 31, wid = tid >> 5;
    const int wm = wid & 3, wn = wid >> 2;
    const int g = lane >> 2, cq = (lane & 3) << 1;

    load_tile<256, 128>(g_in16 + (size_t)row0 * PP, sA0);

    {   float acc[2][4][4];
        gemm_core<256, 64, 128, 4>(g_w16 + W_EZ1, sA0, sB, acc);
        epi_to_smem<256, 64, 4>(acc, bz1, sA1);
    }
    __syncthreads();
    {   float acc[2][4][4];
        gemm_core<256, 64, 64, 4>(g_w16 + W_EZ2, sA1, sB, acc);
        epi_to_smem<256, 64, 4>(acc, bz2, sA0);
    }
    __syncthreads();
    {   float acc[2][4][4];
        gemm_core<256, 64, 64, 4>(g_w16 + W_EZ3, sA0, sB, acc);
        #pragma unroll
        for (int i = 0; i < 2; i++)
            #pragma unroll
            for (int h = 0; h < 2; h++) {
                const int row = wm * 32 + i * 16 + h * 8 + g;
                const int r = row0 + row;
                const int t = r & (TT - 1);
                const int rs = (t % 5 == 0) ? ((r >> 11) * CCH + t / 5) : -1;
                #pragma unroll
                for (int nt = 0; nt < 4; nt++) {
                    const int col = wn * 32 + nt * 8 + cq;
                    float v0 = tanhf(acc[i][nt][2 * h + 0] + __ldg(bz3 + col));
                    float v1 = tanhf(acc[i][nt][2 * h + 1] + __ldg(bz3 + col + 1));
                    *reinterpret_cast<float2*>(z_seq + (size_t)r * MM + col) =
                        make_float2(v0, v1);
                    if (rs >= 0)
                        *reinterpret_cast<float2*>(&g_Z[(size_t)rs * MM + col]) =
                            make_float2(v0, v1);
                }
            }
    }
}

// ---------------------------------------------------------------------------
// mega_step: all 5 recurrence sub-steps in one launch; state in registers.
// Warp-per-row, 16 rows/block (512 thr), NR/16 = 820 blocks.
// Emits z_pred (fp32) and per-step fp16 x snapshots into g_X16s.
// ---------------------------------------------------------------------------
__global__ void __launch_bounds__(512)
mega_step(float* __restrict__ zpred)
{
    __shared__ __align__(16) float sP[P_TOT];
    __shared__ __align__(16) float stz[16][64];

    const int tid = threadIdx.x;
    for (int i = tid; i < P_TOT; i += 512) sP[i] = g_step[i];
    __syncthreads();
    const float*  sWzT = sP + P_WZT;
    const float*  sAzT = sP + P_AZT;
    const float4* sL4  = (const float4*)(sP + P_L);
    const float*  sRT  = sP + P_RT;
    const float*  sAzb = sP + P_AZB;

    const int w = tid >> 5, lane = tid & 31;
    const int r = blockIdx.x * 16 + w;
    const int b = r / CCH, c = r % CCH;

    float zv0 = g_Z[(size_t)r * MM + lane];
    float zv1 = g_Z[(size_t)r * MM + 32 + lane];
    float xv[8];
    #pragma unroll
    for (int k = 0; k < 8; k++) xv[k] = g_X[(size_t)r * KK + lane + 32 * k];

    #pragma unroll 1
    for (int s = 0; s < 5; s++) {
        const int t = 5 * c + s;
        // --- z update ---
        stz[w][lane]      = tanhf(zv0);
        stz[w][lane + 32] = tanhf(zv1);
        __syncwarp();
        float a0 = 0.f, a1 = 0.f;
        #pragma unroll
        for (int i4 = 0; i4 < 16; i4++) {
            float4 tz = *(const float4*)&stz[w][i4 * 4];
            const float* wr = sWzT + (i4 * 4) * 64 + lane;
            a0 = fmaf(tz.x, wr[0],   a0);  a1 = fmaf(tz.x, wr[32],  a1);
            a0 = fmaf(tz.y, wr[64],  a0);  a1 = fmaf(tz.y, wr[96],  a1);
            a0 = fmaf(tz.z, wr[128], a0);  a1 = fmaf(tz.z, wr[160], a1);
            a0 = fmaf(tz.w, wr[192], a0);  a1 = fmaf(tz.w, wr[224], a1);
        }
        float zn0 = zv0 + (a0 - zv0) * 0.01f;
        float zn1 = zv1 + (a1 - zv1) * 0.01f;
        __syncwarp();
        stz[w][lane]      = zn0;
        stz[w][lane + 32] = zn1;
        __syncwarp();
        // --- gate (lanes 0..7) ---
        float sg = 0.f;
        if (lane < 8) {
            float ga = 0.f;
            #pragma unroll 8
            for (int i = 0; i < 64; i++) ga = fmaf(stz[w][i], sAzT[i * 8 + lane], ga);
            sg = 1.f / (1.f + expf(-(ga + sAzb[lane])));
        }
        // --- x low-rank update ---
        float tx[8];
        #pragma unroll
        for (int k = 0; k < 8; k++) tx[k] = tanhf(xv[k]);
        float pu[8] = {0.f,0.f,0.f,0.f,0.f,0.f,0.f,0.f};
        #pragma unroll
        for (int k = 0; k < 8; k++) {
            int j = lane + 32 * k;
            float4 l0 = sL4[j * 3], l1 = sL4[j * 3 + 1];
            pu[0] = fmaf(tx[k], l0.x, pu[0]); pu[1] = fmaf(tx[k], l0.y, pu[1]);
            pu[2] = fmaf(tx[k], l0.z, pu[2]); pu[3] = fmaf(tx[k], l0.w, pu[3]);
            pu[4] = fmaf(tx[k], l1.x, pu[4]); pu[5] = fmaf(tx[k], l1.y, pu[5]);
            pu[6] = fmaf(tx[k], l1.z, pu[6]); pu[7] = fmaf(tx[k], l1.w, pu[7]);
        }
        #pragma unroll
        for (int off = 16; off > 0; off >>= 1)
            #pragma unroll
            for (int q = 0; q < 8; q++)
                pu[q] += __shfl_xor_sync(0xffffffffu, pu[q], off);
        float gu[8];
        #pragma unroll
        for (int q = 0; q < 8; q++)
            gu[q] = pu[q] * __shfl_sync(0xffffffffu, sg, q);
        #pragma unroll
        for (int k = 0; k < 8; k++) {
            int j = lane + 32 * k;
            float acc = 0.f;
            #pragma unroll
            for (int q = 0; q < 8; q++) acc = fmaf(gu[q], sRT[q * 256 + j], acc);
            xv[k] = xv[k] + (acc - xv[k]) * 0.01f;
        }
        zv0 = zn0; zv1 = zn1;
        // --- outputs ---
        if (t < TT) {
            float* zp = zpred + ((size_t)b * TT + t) * MM;
            zp[lane] = zn0; zp[lane + 32] = zn1;
        }
        __half* xd = g_X16s + ((size_t)s * NRP + r) * KK;
        #pragma unroll
        for (int k = 0; k < 8; k++) xd[lane + 32 * k] = __float2half(xv[k]);
    }
}

// ---------------------------------------------------------------------------
// fused_dec: one launch over all 5 steps x NRP rows: X16s -> de1 -> de2 -> x_pred
// ---------------------------------------------------------------------------
__global__ void __launch_bounds__(512, 1)
fused_dec(const float* __restrict__ bd1, const float* __restrict__ bd2,
          float* __restrict__ x_pred)
{
    extern __shared__ __half sm[];
    __half* sA0 = sm;
    __half* sA1 = sm + 33792;
    __half* sB  = sm + 67584;
    const int s    = blockIdx.x / (NRP / 128);
    const int row0 = (blockIdx.x % (NRP / 128)) * 128;
    const int tid = threadIdx.x, lane = tid & 31, wid = tid >> 5;
    const int wm = wid & 3, wn = wid >> 2;
    const int g = lane >> 2, cq = (lane & 3) << 1;

    load_tile<512, 256>(g_X16s + ((size_t)s * NRP + row0) * KK, sA0);

    {   float acc[2][8][4];
        gemm_core<512, 256, 256, 8>(g_w16 + W_DE1, sA0, sB, acc);
        epi_to_smem<512, 256, 8>(acc, bd1, sA1);
    }
    __syncthreads();
    {   float acc[2][4][4];
        gemm_core<512, 128, 256, 4>(g_w16 + W_DE2, sA1, sB, acc);
        #pragma unroll
        for (int i = 0; i < 2; i++)
            #pragma unroll
            for (int h = 0; h < 2; h++) {
                const int row = wm * 32 + i * 16 + h * 8 + g;
                const int r = row0 + row;
                if (r >= NR) continue;
                const int b = r / CCH, c = r % CCH;
                const int t = 5 * c + s;
                if (t >= TT) continue;
                float* crow = x_pred + ((size_t)b * TT + t) * PP;
                #pragma unroll
                for (int nt = 0; nt < 4; nt++) {
                    const int col = wn * 32 + nt * 8 + cq;
                    float v0 = tanhf(acc[i][nt][2 * h + 0] + __ldg(bd2 + col));
                    float v1 = tanhf(acc[i][nt][2 * h + 1] + __ldg(bd2 + col + 1));
                    *reinterpret_cast<float2*>(crow + col) = make_float2(v0, v1);
                }
            }
    }
}

// ---------------------------------------------------------------------------
extern "C" void kernel_launch(void* const* d_in, const int* in_sizes, int n_in,
                              void* d_out, int out_size)
{
    (void)in_sizes; (void)n_in; (void)out_size;
    const float* in_seq = (const float*)d_in[0];
    const float* L      = (const float*)d_in[1];
    const float* Rm     = (const float*)d_in[2];
    const float* Wz     = (const float*)d_in[3];
    const float* Az_w   = (const float*)d_in[4];
    const float* Az_b   = (const float*)d_in[5];
    const float* ex1_w  = (const float*)d_in[6];
    const float* ex1_b  = (const float*)d_in[7];
    const float* ex2_w  = (const float*)d_in[8];
    const float* ex2_b  = (const float*)d_in[9];
    const float* ex3_w  = (const float*)d_in[10];
    const float* ex3_b  = (const float*)d_in[11];
    const float* ez1_w  = (const float*)d_in[12];
    const float* ez1_b  = (const float*)d_in[13];
    const float* ez2_w  = (const float*)d_in[14];
    const float* ez2_b  = (const float*)d_in[15];
    const float* ez3_w  = (const float*)d_in[16];
    const float* ez3_b  = (const float*)d_in[17];
    const float* de1_w  = (const float*)d_in[18];
    const float* de1_b  = (const float*)d_in[19];
    const float* de2_w  = (const float*)d_in[20];
    const float* de2_b  = (const float*)d_in[21];

    float* out    = (float*)d_out;
    float* x_pred = out;
    float* x_rec  = out + (size_t)BB*TT*PP;
    float* z_pred = out + 2*(size_t)BB*TT*PP;
    float* z_seq  = z_pred + (size_t)BB*TT*MM;

    const int SMX = (2 * 128 * 264 + 4 * 256 * 40) * 2;        // 217088 B
    const int SMZ = (128 * 136 + 128 * 72 + 4 * 64 * 40) * 2;  // 73728 B
    cudaFuncSetAttribute(fused_x,   cudaFuncAttributeMaxDynamicSharedMemorySize, SMX);
    cudaFuncSetAttribute(fused_dec, cudaFuncAttributeMaxDynamicSharedMemorySize, SMX);
    cudaFuncSetAttribute(fused_z,   cudaFuncAttributeMaxDynamicSharedMemorySize, SMZ);

    // 1. conversions + step-weight transposes
    {
        const int TOT = NROWS*PP/4 + W_TOTAL/4 + P_TOT;
        conv_kernel<<<(TOT + 255) / 256, 256>>>(in_seq, ex1_w, ex2_w, ex3_w,
                                                ez1_w, ez2_w, ez3_w, de1_w, de2_w,
                                                Wz, Az_w, Az_b, L, Rm);
    }

    // 2. fused encoder->decoder chains (also seed scan state)
    fused_x<<<NROWS/128, 512, SMX>>>(ex1_b, ex2_b, ex3_b, de1_b, de2_b, x_rec);
    fused_z<<<NROWS/128, 256, SMZ>>>(ez1_b, ez2_b, ez3_b, z_seq);

    // 3. all 5 recurrence sub-steps in one launch
    mega_step<<<NR/16, 512>>>(z_pred);

    // 4. one decoder launch over all 5 step snapshots
    fused_dec<<<5 * (NRP/128), 512, SMX>>>(de1_b, de2_b, x_pred);
}

// round 7
// speedup vs baseline: 9.5524x; 1.1675x over previous
#include <cuda_runtime.h>
#include <cuda_fp16.h>
#include <math.h>
#include <stdint.h>

// Problem constants
#define BB 32
#define TT 2048
#define PP 128
#define KK 256
#define MM 64
#define CCH 410            // independent 5-step chunks
#define NR (BB*CCH)        // 13120 state rows
#define NRP 13184          // NR padded to 128 multiple
#define NROWS (BB*TT)      // 65536 encoder rows

// fp16 weight pack offsets (in halfs)
#define W_EX1 0
#define W_EX2 32768
#define W_EX3 98304
#define W_EZ1 163840
#define W_EZ2 172032
#define W_EZ3 176128
#define W_DE1 180224
#define W_DE2 245760
#define W_TOTAL 278528

// fp32 step-weight pack offsets (floats)
#define P_WZT 0        // 64x64 transposed:  [i*64+j] = Wz[j*64+i]
#define P_AZT 4096     // 64x8  transposed:  [i*8+r]  = Az[r*64+i]
#define P_L   4608     // 256x12 (pitch 12, cols 0..7 = L row)
#define P_RT  7680     // 8x256 transposed:  [r*256+j] = Rm[j*8+r]
#define P_AZB 9728     // 8
#define P_TOT 9736

// Scratch (device globals; zero-initialized)
__device__ __half g_in16[NROWS*PP];
__device__ __half g_w16[W_TOTAL];
__device__ float  g_step[P_TOT];
__device__ float  g_X[NRP*KK];                  // fp32 scan-state init; pad rows 0
__device__ float  g_Z[NR*MM];
__device__ __half g_X16s[(size_t)5*NRP*KK];     // per-step x snapshots; pad rows 0

// ---------------------------------------------------------------------------
// asm helpers
// ---------------------------------------------------------------------------
__device__ __forceinline__ void cpa16(uint32_t dst, const void* src) {
    asm volatile("cp.async.cg.shared.global [%0], [%1], 16;\n"
                 :: "r"(dst), "l"(src));
}
__device__ __forceinline__ void commitg() {
    asm volatile("cp.async.commit_group;\n" ::: "memory");
}
template<int N> __device__ __forceinline__ void waitg() {
    asm volatile("cp.async.wait_group %0;\n" :: "n"(N) : "memory");
}
__device__ __forceinline__ void ldsm4(uint32_t* r, uint32_t addr) {
    asm volatile("ldmatrix.sync.aligned.m8n8.x4.shared.b16 {%0,%1,%2,%3}, [%4];\n"
        : "=r"(r[0]), "=r"(r[1]), "=r"(r[2]), "=r"(r[3]) : "r"(addr));
}
__device__ __forceinline__ void mma16816(float* c, const uint32_t* a,
                                         uint32_t b0, uint32_t b1) {
    asm volatile(
      "mma.sync.aligned.m16n8k16.row.col.f32.f16.f16.f32 "
      "{%0,%1,%2,%3}, {%4,%5,%6,%7}, {%8,%9}, {%0,%1,%2,%3};\n"
      : "+f"(c[0]), "+f"(c[1]), "+f"(c[2]), "+f"(c[3])
      : "r"(a[0]), "r"(a[1]), "r"(a[2]), "r"(a[3]), "r"(b0), "r"(b1));
}

// ---------------------------------------------------------------------------
// One-time conversion: in_seq + weights -> fp16; step weights -> transposed pack
// ---------------------------------------------------------------------------
__global__ void conv_kernel(const float* __restrict__ in_seq,
                            const float* __restrict__ ex1, const float* __restrict__ ex2,
                            const float* __restrict__ ex3, const float* __restrict__ ez1,
                            const float* __restrict__ ez2, const float* __restrict__ ez3,
                            const float* __restrict__ de1, const float* __restrict__ de2,
                            const float* __restrict__ Wz,  const float* __restrict__ Azw,
                            const float* __restrict__ Azb, const float* __restrict__ Lw,
                            const float* __restrict__ Rm)
{
    const int NIN4 = NROWS*PP/4;
    int i4 = blockIdx.x * blockDim.x + threadIdx.x;
    if (i4 < NIN4) {
        float4 v = reinterpret_cast<const float4*>(in_seq)[i4];
        __half2 a = __floats2half2_rn(v.x, v.y), b = __floats2half2_rn(v.z, v.w);
        uint2 u = { *reinterpret_cast<unsigned*>(&a), *reinterpret_cast<unsigned*>(&b) };
        reinterpret_cast<uint2*>(g_in16)[i4] = u;
        return;
    }
    int j = (i4 - NIN4) * 4;
    if (j < W_TOTAL) {
        const float* src; int off;
        if      (j < W_EX2) { src = ex1; off = W_EX1; }
        else if (j < W_EX3) { src = ex2; off = W_EX2; }
        else if (j < W_EZ1) { src = ex3; off = W_EX3; }
        else if (j < W_EZ2) { src = ez1; off = W_EZ1; }
        else if (j < W_EZ3) { src = ez2; off = W_EZ2; }
        else if (j < W_DE1) { src = ez3; off = W_EZ3; }
        else if (j < W_DE2) { src = de1; off = W_DE1; }
        else                { src = de2; off = W_DE2; }
        float4 v = reinterpret_cast<const float4*>(src)[(j - off) >> 2];
        __half2 a = __floats2half2_rn(v.x, v.y), b = __floats2half2_rn(v.z, v.w);
        uint2 u = { *reinterpret_cast<unsigned*>(&a), *reinterpret_cast<unsigned*>(&b) };
        *reinterpret_cast<uint2*>(&g_w16[j]) = u;
        return;
    }
    int sidx = i4 - NIN4 - W_TOTAL/4;
    if (sidx >= P_TOT) return;
    float v;
    if (sidx < P_AZT) {
        v = Wz[(sidx & 63)*64 + (sidx >> 6)];
    } else if (sidx < P_L) {
        int q = sidx - P_AZT;
        v = Azw[(q & 7)*64 + (q >> 3)];
    } else if (sidx < P_RT) {
        int q = sidx - P_L;
        int row = q / 12, col = q % 12;
        v = (col < 8) ? Lw[row*8 + col] : 0.f;
    } else if (sidx < P_AZB) {
        int q = sidx - P_RT;
        v = Rm[(q & 255)*8 + (q >> 8)];
    } else {
        v = Azb[sidx - P_AZB];
    }
    g_step[sidx] = v;
}

// ---------------------------------------------------------------------------
// Load a 128 x KH fp16 gmem tile into pitched smem (pitch = KH + 8)
// ---------------------------------------------------------------------------
template<int THREADS, int KH>
__device__ __forceinline__ void load_tile(const __half* __restrict__ g, __half* sDst)
{
    constexpr int AP = KH + 8;
    constexpr int CHT = 128 * KH / 8;
    const int tid = threadIdx.x;
    uint32_t d = (uint32_t)__cvta_generic_to_shared(sDst);
    #pragma unroll
    for (int c = tid; c < CHT; c += THREADS) {
        int row = c / (KH / 8), off = (c % (KH / 8)) * 8;
        cpa16(d + (uint32_t)((row * AP + off) * 2), g + (size_t)row * KH + off);
    }
    commitg(); waitg<0>(); __syncthreads();
}

// ---------------------------------------------------------------------------
// GEMM core: acc(128 x Nd) += smemA(128 x Kd, pitch Kd+8) @ gW(Nd x Kd)^T
// ---------------------------------------------------------------------------
template<int THREADS, int Nd, int Kd, int NT>
__device__ __forceinline__ void gemm_core(const __half* __restrict__ gW,
                                          const __half* sA, __half* sB,
                                          float (&acc)[2][NT][4])
{
    constexpr int BK = 32, NS = 4, BP = 40, AP = Kd + 8;
    constexpr int NWN = THREADS / 128;
    constexpr int WN = Nd / NWN;
    static_assert(NT == WN / 8, "NT mismatch");
    constexpr int S = Kd / BK;
    constexpr int CH = Nd * BK / 8;

    const int tid = threadIdx.x, lane = tid & 31, wid = tid >> 5;
    const int wm = wid & 3, wn = wid >> 2;
    const uint32_t aBase = (uint32_t)__cvta_generic_to_shared(sA);
    const uint32_t bBase = (uint32_t)__cvta_generic_to_shared(sB);
    const int arow = wm * 32 + (lane & 15);
    const int akof = (lane >> 4) << 3;
    const int brow = wn * WN + (lane & 7) + ((lane >> 4) << 3);
    const int bkof = ((lane >> 3) & 1) << 3;

    #pragma unroll
    for (int i = 0; i < 2; i++)
        #pragma unroll
        for (int j = 0; j < NT; j++)
            #pragma unroll
            for (int q = 0; q < 4; q++) acc[i][j][q] = 0.f;

    auto issueB = [&](int s, int slot) {
        #pragma unroll
        for (int c = tid; c < CH; c += THREADS) {
            int row = c >> 2, off = (c & 3) << 3;
            cpa16(bBase + (uint32_t)(((slot * Nd + row) * BP + off) * 2),
                  gW + (size_t)row * Kd + s * BK + off);
        }
    };

    #pragma unroll
    for (int i = 0; i < NS - 1; i++) { if (i < S) issueB(i, i); commitg(); }

    #pragma unroll
    for (int s = 0; s < S; s++) {
        waitg<NS - 2>();
        __syncthreads();
        if (s + NS - 1 < S) issueB(s + NS - 1, (s + NS - 1) & (NS - 1));
        commitg();
        const int slot = s & (NS - 1);
        #pragma unroll
        for (int kk = 0; kk < BK; kk += 16) {
            uint32_t af[2][4];
            uint32_t aa = aBase + (uint32_t)((arow * AP + s * BK + kk + akof) * 2);
            ldsm4(af[0], aa);
            ldsm4(af[1], aa + 16 * AP * 2);
            #pragma unroll
            for (int j2 = 0; j2 < NT / 2; j2++) {
                uint32_t bf[4];
                ldsm4(bf, bBase + (uint32_t)(((slot * Nd + brow + j2 * 16) * BP + kk + bkof) * 2));
                mma16816(acc[0][2 * j2],     af[0], bf[0], bf[1]);
                mma16816(acc[0][2 * j2 + 1], af[0], bf[2], bf[3]);
                mma16816(acc[1][2 * j2],     af[1], bf[0], bf[1]);
                mma16816(acc[1][2 * j2 + 1], af[1], bf[2], bf[3]);
            }
        }
    }
}

// ---------------------------------------------------------------------------
// Epilogue: tanh(acc + bias) -> pitched smem (pitch Nd + 8)
// ---------------------------------------------------------------------------
template<int THREADS, int Nd, int NT>
__device__ __forceinline__ void epi_to_smem(float (&acc)[2][NT][4],
        const float* __restrict__ bias, __half* sOut)
{
    constexpr int NWN = THREADS / 128, WN = Nd / NWN, OP = Nd + 8;
    const int tid = threadIdx.x, lane = tid & 31, wid = tid >> 5;
    const int wm = wid & 3, wn = wid >> 2;
    const int g = lane >> 2, cq = (lane & 3) << 1;
    #pragma unroll
    for (int i = 0; i < 2; i++)
        #pragma unroll
        for (int h = 0; h < 2; h++) {
            const int row = wm * 32 + i * 16 + h * 8 + g;
            #pragma unroll
            for (int nt = 0; nt < NT; nt++) {
                const int col = wn * WN + nt * 8 + cq;
                float v0 = tanhf(acc[i][nt][2 * h + 0] + __ldg(bias + col));
                float v1 = tanhf(acc[i][nt][2 * h + 1] + __ldg(bias + col + 1));
                *reinterpret_cast<__half2*>(sOut + row * OP + col) =
                    __floats2half2_rn(v0, v1);
            }
        }
}

// ---------------------------------------------------------------------------
// fused_x: per 128-row tile: in16 -> ex1 -> ex2 -> ex3 (state init fp32)
//          -> de1 -> de2 -> x_rec (fp32)
// ---------------------------------------------------------------------------
__global__ void __launch_bounds__(512, 1)
fused_x(const float* __restrict__ bx1, const float* __restrict__ bx2,
        const float* __restrict__ bx3, const float* __restrict__ bd1,
        const float* __restrict__ bd2, float* __restrict__ x_rec)
{
    extern __shared__ __half sm[];
    __half* sA0 = sm;
    __half* sA1 = sm + 33792;
    __half* sB  = sm + 67584;
    const int row0 = blockIdx.x * 128;
    const int tid = threadIdx.x, lane = tid & 31, wid = tid >> 5;
    const int wm = wid & 3, wn = wid >> 2;
    const int g = lane >> 2, cq = (lane & 3) << 1;

    load_tile<512, 128>(g_in16 + (size_t)row0 * PP, sA0);

    {   float acc[2][8][4];
        gemm_core<512, 256, 128, 8>(g_w16 + W_EX1, sA0, sB, acc);
        epi_to_smem<512, 256, 8>(acc, bx1, sA1);
    }
    __syncthreads();
    {   float acc[2][8][4];
        gemm_core<512, 256, 256, 8>(g_w16 + W_EX2, sA1, sB, acc);
        epi_to_smem<512, 256, 8>(acc, bx2, sA0);
    }
    __syncthreads();
    {   // ex3: activation to sA1 + fp32 scan-state init
        float acc[2][8][4];
        gemm_core<512, 256, 256, 8>(g_w16 + W_EX3, sA0, sB, acc);
        #pragma unroll
        for (int i = 0; i < 2; i++)
            #pragma unroll
            for (int h = 0; h < 2; h++) {
                const int row = wm * 32 + i * 16 + h * 8 + g;
                const int r = row0 + row;
                const int t = r & (TT - 1);
                const int rs = (t % 5 == 0) ? ((r >> 11) * CCH + t / 5) : -1;
                #pragma unroll
                for (int nt = 0; nt < 8; nt++) {
                    const int col = wn * 64 + nt * 8 + cq;
                    float v0 = tanhf(acc[i][nt][2 * h + 0] + __ldg(bx3 + col));
                    float v1 = tanhf(acc[i][nt][2 * h + 1] + __ldg(bx3 + col + 1));
                    *reinterpret_cast<__half2*>(sA1 + row * 264 + col) =
                        __floats2half2_rn(v0, v1);
                    if (rs >= 0)
                        *reinterpret_cast<float2*>(&g_X[(size_t)rs * KK + col]) =
                            make_float2(v0, v1);
                }
            }
    }
    __syncthreads();
    {   float acc[2][8][4];
        gemm_core<512, 256, 256, 8>(g_w16 + W_DE1, sA1, sB, acc);
        epi_to_smem<512, 256, 8>(acc, bd1, sA0);
    }
    __syncthreads();
    {   // de2 -> x_rec (fp32 dense)
        float acc[2][4][4];
        gemm_core<512, 128, 256, 4>(g_w16 + W_DE2, sA0, sB, acc);
        #pragma unroll
        for (int i = 0; i < 2; i++)
            #pragma unroll
            for (int h = 0; h < 2; h++) {
                const int row = wm * 32 + i * 16 + h * 8 + g;
                const int r = row0 + row;
                #pragma unroll
                for (int nt = 0; nt < 4; nt++) {
                    const int col = wn * 32 + nt * 8 + cq;
                    float v0 = tanhf(acc[i][nt][2 * h + 0] + __ldg(bd2 + col));
                    float v1 = tanhf(acc[i][nt][2 * h + 1] + __ldg(bd2 + col + 1));
                    *reinterpret_cast<float2*>(x_rec + (size_t)r * PP + col) =
                        make_float2(v0, v1);
                }
            }
    }
}

// ---------------------------------------------------------------------------
// fused_z: in16 -> ez1 -> ez2 -> ez3 -> z_seq (fp32) + Z init
// ---------------------------------------------------------------------------
__global__ void __launch_bounds__(256)
fused_z(const float* __restrict__ bz1, const float* __restrict__ bz2,
        const float* __restrict__ bz3, float* __restrict__ z_seq)
{
    extern __shared__ __half sm[];
    __half* sA0 = sm;
    __half* sA1 = sm + 17408;
    __half* sB  = sm + 26624;
    const int row0 = blockIdx.x * 128;
    const int tid = threadIdx.x, lane = tid & 31, wid = tid >> 5;
    const int wm = wid & 3, wn = wid >> 2;
    const int g = lane >> 2, cq = (lane & 3) << 1;

    load_tile<256, 128>(g_in16 + (size_t)row0 * PP, sA0);

    {   float acc[2][4][4];
        gemm_core<256, 64, 128, 4>(g_w16 + W_EZ1, sA0, sB, acc);
        epi_to_smem<256, 64, 4>(acc, bz1, sA1);
    }
    __syncthreads();
    {   float acc[2][4][4];
        gemm_core<256, 64, 64, 4>(g_w16 + W_EZ2, sA1, sB, acc);
        epi_to_smem<256, 64, 4>(acc, bz2, sA0);
    }
    __syncthreads();
    {   float acc[2][4][4];
        gemm_core<256, 64, 64, 4>(g_w16 + W_EZ3, sA0, sB, acc);
        #pragma unroll
        for (int i = 0; i < 2; i++)
            #pragma unroll
            for (int h = 0; h < 2; h++) {
                const int row = wm * 32 + i * 16 + h * 8 + g;
                const int r = row0 + row;
                const int t = r & (TT - 1);
                const int rs = (t % 5 == 0) ? ((r >> 11) * CCH + t / 5) : -1;
                #pragma unroll
                for (int nt = 0; nt < 4; nt++) {
                    const int col = wn * 32 + nt * 8 + cq;
                    float v0 = tanhf(acc[i][nt][2 * h + 0] + __ldg(bz3 + col));
                    float v1 = tanhf(acc[i][nt][2 * h + 1] + __ldg(bz3 + col + 1));
                    *reinterpret_cast<float2*>(z_seq + (size_t)r * MM + col) =
                        make_float2(v0, v1);
                    if (rs >= 0)
                        *reinterpret_cast<float2*>(&g_Z[(size_t)rs * MM + col]) =
                            make_float2(v0, v1);
                }
            }
    }
}

// ---------------------------------------------------------------------------
// mega_step: all 5 recurrence sub-steps; 4 rows per warp (weight LDS amortized
// 4x), 8 warps/block, NR/32 = 410 blocks. State in registers across steps.
// Accumulation orders identical to the warp-per-row version (bit-exact).
// ---------------------------------------------------------------------------
__global__ void __launch_bounds__(256, 2)
mega_step(float* __restrict__ zpred)
{
    __shared__ __align__(16) float sP[P_TOT];
    __shared__ __align__(16) float stz[8][4][64];

    const int tid = threadIdx.x;
    for (int i = tid; i < P_TOT; i += 256) sP[i] = g_step[i];
    __syncthreads();
    const float*  sWzT = sP + P_WZT;
    const float*  sAzT = sP + P_AZT;
    const float4* sL4  = (const float4*)(sP + P_L);
    const float*  sRT  = sP + P_RT;
    const float*  sAzb = sP + P_AZB;

    const int w = tid >> 5, lane = tid & 31;
    const int r0 = (blockIdx.x * 8 + w) * 4;
    const int gr = lane >> 3, gq = lane & 7;    // gate mapping: lane = gr*8+gq

    int tbase[4]; size_t zoff[4];
    float zv0[4], zv1[4], xv[4][8];
    #pragma unroll
    for (int r = 0; r < 4; r++) {
        const int rr = r0 + r;
        const int b = rr / CCH, c = rr % CCH;
        tbase[r] = 5 * c;
        zoff[r]  = ((size_t)b * TT) * MM;
        zv0[r] = g_Z[(size_t)rr * MM + lane];
        zv1[r] = g_Z[(size_t)rr * MM + 32 + lane];
        #pragma unroll
        for (int k = 0; k < 8; k++)
            xv[r][k] = g_X[(size_t)rr * KK + lane + 32 * k];
    }

    #pragma unroll 1
    for (int s = 0; s < 5; s++) {
        // --- stage tanh(z) ---
        #pragma unroll
        for (int r = 0; r < 4; r++) {
            stz[w][r][lane]      = tanhf(zv0[r]);
            stz[w][r][lane + 32] = tanhf(zv1[r]);
        }
        __syncwarp();
        // --- z matvec: a[r] = tanh(z_r) @ WzT, weights shared across rows ---
        float a0[4] = {0.f,0.f,0.f,0.f}, a1[4] = {0.f,0.f,0.f,0.f};
        #pragma unroll
        for (int i4 = 0; i4 < 16; i4++) {
            float4 tz[4];
            #pragma unroll
            for (int r = 0; r < 4; r++)
                tz[r] = *(const float4*)&stz[w][r][i4 * 4];
            const float* wr = sWzT + (i4 * 4) * 64 + lane;
            #pragma unroll
            for (int ii = 0; ii < 4; ii++) {
                const float w0 = wr[ii * 64], w1 = wr[ii * 64 + 32];
                const float c0 = (ii == 0) ? tz[0].x : (ii == 1) ? tz[0].y
                               : (ii == 2) ? tz[0].z : tz[0].w;
                const float c1 = (ii == 0) ? tz[1].x : (ii == 1) ? tz[1].y
                               : (ii == 2) ? tz[1].z : tz[1].w;
                const float c2 = (ii == 0) ? tz[2].x : (ii == 1) ? tz[2].y
                               : (ii == 2) ? tz[2].z : tz[2].w;
                const float c3 = (ii == 0) ? tz[3].x : (ii == 1) ? tz[3].y
                               : (ii == 2) ? tz[3].z : tz[3].w;
                a0[0] = fmaf(c0, w0, a0[0]);  a1[0] = fmaf(c0, w1, a1[0]);
                a0[1] = fmaf(c1, w0, a0[1]);  a1[1] = fmaf(c1, w1, a1[1]);
                a0[2] = fmaf(c2, w0, a0[2]);  a1[2] = fmaf(c2, w1, a1[2]);
                a0[3] = fmaf(c3, w0, a0[3]);  a1[3] = fmaf(c3, w1, a1[3]);
            }
        }
        #pragma unroll
        for (int r = 0; r < 4; r++) {
            zv0[r] = zv0[r] + (a0[r] - zv0[r]) * 0.01f;
            zv1[r] = zv1[r] + (a1[r] - zv1[r]) * 0.01f;
        }
        __syncwarp();
        // --- stage z' for gate ---
        #pragma unroll
        for (int r = 0; r < 4; r++) {
            stz[w][r][lane]      = zv0[r];
            stz[w][r][lane + 32] = zv1[r];
        }
        __syncwarp();
        // --- gate: lane (gr, gq) computes sigmoid(z'_gr @ Az_gq + b_gq) ---
        float ga = 0.f;
        {
            const float* zr = stz[w][gr];
            #pragma unroll 8
            for (int i = 0; i < 64; i++)
                ga = fmaf(zr[i], sAzT[i * 8 + gq], ga);
        }
        const float sg = 1.f / (1.f + expf(-(ga + sAzb[gq])));
        // --- L projection: gu[r][q] partials, weights shared across rows ---
        float gu[4][8];
        #pragma unroll
        for (int r = 0; r < 4; r++)
            #pragma unroll
            for (int q = 0; q < 8; q++) gu[r][q] = 0.f;
        #pragma unroll
        for (int k = 0; k < 8; k++) {
            const int j = lane + 32 * k;
            const float4 l0 = sL4[j * 3], l1 = sL4[j * 3 + 1];
            #pragma unroll
            for (int r = 0; r < 4; r++) {
                const float tx = tanhf(xv[r][k]);
                gu[r][0] = fmaf(tx, l0.x, gu[r][0]);
                gu[r][1] = fmaf(tx, l0.y, gu[r][1]);
                gu[r][2] = fmaf(tx, l0.z, gu[r][2]);
                gu[r][3] = fmaf(tx, l0.w, gu[r][3]);
                gu[r][4] = fmaf(tx, l1.x, gu[r][4]);
                gu[r][5] = fmaf(tx, l1.y, gu[r][5]);
                gu[r][6] = fmaf(tx, l1.z, gu[r][6]);
                gu[r][7] = fmaf(tx, l1.w, gu[r][7]);
            }
        }
        // --- butterfly reduce (same order as before: 16,8,4,2,1) ---
        #pragma unroll
        for (int off = 16; off > 0; off >>= 1)
            #pragma unroll
            for (int r = 0; r < 4; r++)
                #pragma unroll
                for (int q = 0; q < 8; q++)
                    gu[r][q] += __shfl_xor_sync(0xffffffffu, gu[r][q], off);
        // --- apply gate: gate(r,q) lives in lane r*8+q ---
        #pragma unroll
        for (int r = 0; r < 4; r++)
            #pragma unroll
            for (int q = 0; q < 8; q++)
                gu[r][q] *= __shfl_sync(0xffffffffu, sg, r * 8 + q);
        // --- R projection: weights shared across rows ---
        #pragma unroll
        for (int k = 0; k < 8; k++) {
            const int j = lane + 32 * k;
            float acc[4] = {0.f,0.f,0.f,0.f};
            #pragma unroll
            for (int q = 0; q < 8; q++) {
                const float wv = sRT[q * 256 + j];
                acc[0] = fmaf(gu[0][q], wv, acc[0]);
                acc[1] = fmaf(gu[1][q], wv, acc[1]);
                acc[2] = fmaf(gu[2][q], wv, acc[2]);
                acc[3] = fmaf(gu[3][q], wv, acc[3]);
            }
            #pragma unroll
            for (int r = 0; r < 4; r++)
                xv[r][k] = xv[r][k] + (acc[r] - xv[r][k]) * 0.01f;
        }
        // --- outputs ---
        #pragma unroll
        for (int r = 0; r < 4; r++) {
            const int t = tbase[r] + s;
            if (t < TT) {
                float* zp = zpred + zoff[r] + (size_t)t * MM;
                zp[lane]      = zv0[r];
                zp[lane + 32] = zv1[r];
            }
            __half* xd = g_X16s + ((size_t)s * NRP + (r0 + r)) * KK;
            #pragma unroll
            for (int k = 0; k < 8; k++)
                xd[lane + 32 * k] = __float2half(xv[r][k]);
        }
    }
}

// ---------------------------------------------------------------------------
// fused_dec: one launch over all 5 steps x NRP rows: X16s -> de1 -> de2 -> x_pred
// ---------------------------------------------------------------------------
__global__ void __launch_bounds__(512, 1)
fused_dec(const float* __restrict__ bd1, const float* __restrict__ bd2,
          float* __restrict__ x_pred)
{
    extern __shared__ __half sm[];
    __half* sA0 = sm;
    __half* sA1 = sm + 33792;
    __half* sB  = sm + 67584;
    const int s    = blockIdx.x / (NRP / 128);
    const int row0 = (blockIdx.x % (NRP / 128)) * 128;
    const int tid = threadIdx.x, lane = tid & 31, wid = tid >> 5;
    const int wm = wid & 3, wn = wid >> 2;
    const int g = lane >> 2, cq = (lane & 3) << 1;

    load_tile<512, 256>(g_X16s + ((size_t)s * NRP + row0) * KK, sA0);

    {   float acc[2][8][4];
        gemm_core<512, 256, 256, 8>(g_w16 + W_DE1, sA0, sB, acc);
        epi_to_smem<512, 256, 8>(acc, bd1, sA1);
    }
    __syncthreads();
    {   float acc[2][4][4];
        gemm_core<512, 128, 256, 4>(g_w16 + W_DE2, sA1, sB, acc);
        #pragma unroll
        for (int i = 0; i < 2; i++)
            #pragma unroll
            for (int h = 0; h < 2; h++) {
                const int row = wm * 32 + i * 16 + h * 8 + g;
                const int r = row0 + row;
                if (r >= NR) continue;
                const int b = r / CCH, c = r % CCH;
                const int t = 5 * c + s;
                if (t >= TT) continue;
                float* crow = x_pred + ((size_t)b * TT + t) * PP;
                #pragma unroll
                for (int nt = 0; nt < 4; nt++) {
                    const int col = wn * 32 + nt * 8 + cq;
                    float v0 = tanhf(acc[i][nt][2 * h + 0] + __ldg(bd2 + col));
                    float v1 = tanhf(acc[i][nt][2 * h + 1] + __ldg(bd2 + col + 1));
                    *reinterpret_cast<float2*>(crow + col) = make_float2(v0, v1);
                }
            }
    }
}

// ---------------------------------------------------------------------------
extern "C" void kernel_launch(void* const* d_in, const int* in_sizes, int n_in,
                              void* d_out, int out_size)
{
    (void)in_sizes; (void)n_in; (void)out_size;
    const float* in_seq = (const float*)d_in[0];
    const float* L      = (const float*)d_in[1];
    const float* Rm     = (const float*)d_in[2];
    const float* Wz     = (const float*)d_in[3];
    const float* Az_w   = (const float*)d_in[4];
    const float* Az_b   = (const float*)d_in[5];
    const float* ex1_w  = (const float*)d_in[6];
    const float* ex1_b  = (const float*)d_in[7];
    const float* ex2_w  = (const float*)d_in[8];
    const float* ex2_b  = (const float*)d_in[9];
    const float* ex3_w  = (const float*)d_in[10];
    const float* ex3_b  = (const float*)d_in[11];
    const float* ez1_w  = (const float*)d_in[12];
    const float* ez1_b  = (const float*)d_in[13];
    const float* ez2_w  = (const float*)d_in[14];
    const float* ez2_b  = (const float*)d_in[15];
    const float* ez3_w  = (const float*)d_in[16];
    const float* ez3_b  = (const float*)d_in[17];
    const float* de1_w  = (const float*)d_in[18];
    const float* de1_b  = (const float*)d_in[19];
    const float* de2_w  = (const float*)d_in[20];
    const float* de2_b  = (const float*)d_in[21];

    float* out    = (float*)d_out;
    float* x_pred = out;
    float* x_rec  = out + (size_t)BB*TT*PP;
    float* z_pred = out + 2*(size_t)BB*TT*PP;
    float* z_seq  = z_pred + (size_t)BB*TT*MM;

    const int SMX = (2 * 128 * 264 + 4 * 256 * 40) * 2;        // 217088 B
    const int SMZ = (128 * 136 + 128 * 72 + 4 * 64 * 40) * 2;  // 73728 B
    cudaFuncSetAttribute(fused_x,   cudaFuncAttributeMaxDynamicSharedMemorySize, SMX);
    cudaFuncSetAttribute(fused_dec, cudaFuncAttributeMaxDynamicSharedMemorySize, SMX);
    cudaFuncSetAttribute(fused_z,   cudaFuncAttributeMaxDynamicSharedMemorySize, SMZ);

    // 1. conversions + step-weight transposes
    {
        const int TOT = NROWS*PP/4 + W_TOTAL/4 + P_TOT;
        conv_kernel<<<(TOT + 255) / 256, 256>>>(in_seq, ex1_w, ex2_w, ex3_w,
                                                ez1_w, ez2_w, ez3_w, de1_w, de2_w,
                                                Wz, Az_w, Az_b, L, Rm);
    }

    // 2. fused encoder->decoder chains (also seed scan state)
    fused_x<<<NROWS/128, 512, SMX>>>(ex1_b, ex2_b, ex3_b, de1_b, de2_b, x_rec);
    fused_z<<<NROWS/128, 256, SMZ>>>(ez1_b, ez2_b, ez3_b, z_seq);

    // 3. all 5 recurrence sub-steps in one launch (4 rows/warp)
    mega_step<<<NR/32, 256>>>(z_pred);

    // 4. one decoder launch over all 5 step snapshots
    fused_dec<<<5 * (NRP/128), 512, SMX>>>(de1_b, de2_b, x_pred);
}

// round 8
// speedup vs baseline: 10.1859x; 1.0663x over previous
#include <cuda_runtime.h>
#include <cuda_fp16.h>
#include <math.h>
#include <stdint.h>

// Problem constants
#define BB 32
#define TT 2048
#define PP 128
#define KK 256
#define MM 64
#define CCH 410            // independent 5-step chunks
#define NR (BB*CCH)        // 13120 state rows
#define NRP 13184          // NR padded to 128 multiple
#define NROWS (BB*TT)      // 65536 encoder rows

// fp16 weight pack offsets (in halfs)
#define W_EX1 0
#define W_EX2 32768
#define W_EX3 98304
#define W_EZ1 163840
#define W_EZ2 172032
#define W_EZ3 176128
#define W_DE1 180224
#define W_DE2 245760
#define W_TOTAL 278528

// fp32 step-weight pack offsets (floats)
#define P_WZT 0        // 64x64 transposed
#define P_AZT 4096     // 64x8 transposed
#define P_L   4608     // 256x12 (pitch 12)
#define P_RT  7680     // 8x256 transposed
#define P_AZB 9728     // 8
#define P_TOT 9736

// Scratch (device globals; zero-initialized)
__device__ __half g_in16[NROWS*PP];
__device__ __half g_w16[W_TOTAL];
__device__ float  g_step[P_TOT];
__device__ float  g_X[NRP*KK];                  // fp32 scan-state init; pad rows 0
__device__ float  g_Z[NR*MM];
__device__ __half g_X16s[(size_t)5*NRP*KK];     // per-step x snapshots; pad rows 0

// ---------------------------------------------------------------------------
// helpers
// ---------------------------------------------------------------------------
__device__ __forceinline__ void cpa16(uint32_t dst, const void* src) {
    asm volatile("cp.async.cg.shared.global [%0], [%1], 16;\n"
                 :: "r"(dst), "l"(src));
}
__device__ __forceinline__ void commitg() {
    asm volatile("cp.async.commit_group;\n" ::: "memory");
}
template<int N> __device__ __forceinline__ void waitg() {
    asm volatile("cp.async.wait_group %0;\n" :: "n"(N) : "memory");
}
__device__ __forceinline__ void ldsm4(uint32_t* r, uint32_t addr) {
    asm volatile("ldmatrix.sync.aligned.m8n8.x4.shared.b16 {%0,%1,%2,%3}, [%4];\n"
        : "=r"(r[0]), "=r"(r[1]), "=r"(r[2]), "=r"(r[3]) : "r"(addr));
}
__device__ __forceinline__ void mma16816(float* c, const uint32_t* a,
                                         uint32_t b0, uint32_t b1) {
    asm volatile(
      "mma.sync.aligned.m16n8k16.row.col.f32.f16.f16.f32 "
      "{%0,%1,%2,%3}, {%4,%5,%6,%7}, {%8,%9}, {%0,%1,%2,%3};\n"
      : "+f"(c[0]), "+f"(c[1]), "+f"(c[2]), "+f"(c[3])
      : "r"(a[0]), "r"(a[1]), "r"(a[2]), "r"(a[3]), "r"(b0), "r"(b1));
}
// accurate-enough fast tanh (abs err ~1e-7): used for all output-facing tanh
__device__ __forceinline__ float ftanh(float x) {
    float e = __expf(2.0f * x);
    return 1.0f - __fdividef(2.0f, e + 1.0f);
}
// hardware tanh approx (1 MUFU): used only inside the recurrence where the
// error is attenuated by /100 before reaching any output
__device__ __forceinline__ float htanh(float x) {
    float y; asm("tanh.approx.f32 %0, %1;" : "=f"(y) : "f"(x)); return y;
}

// ---------------------------------------------------------------------------
// One-time conversion: in_seq + weights -> fp16; step weights -> transposed pack
// ---------------------------------------------------------------------------
__global__ void conv_kernel(const float* __restrict__ in_seq,
                            const float* __restrict__ ex1, const float* __restrict__ ex2,
                            const float* __restrict__ ex3, const float* __restrict__ ez1,
                            const float* __restrict__ ez2, const float* __restrict__ ez3,
                            const float* __restrict__ de1, const float* __restrict__ de2,
                            const float* __restrict__ Wz,  const float* __restrict__ Azw,
                            const float* __restrict__ Azb, const float* __restrict__ Lw,
                            const float* __restrict__ Rm)
{
    const int NIN4 = NROWS*PP/4;
    int i4 = blockIdx.x * blockDim.x + threadIdx.x;
    if (i4 < NIN4) {
        float4 v = reinterpret_cast<const float4*>(in_seq)[i4];
        __half2 a = __floats2half2_rn(v.x, v.y), b = __floats2half2_rn(v.z, v.w);
        uint2 u = { *reinterpret_cast<unsigned*>(&a), *reinterpret_cast<unsigned*>(&b) };
        reinterpret_cast<uint2*>(g_in16)[i4] = u;
        return;
    }
    int j = (i4 - NIN4) * 4;
    if (j < W_TOTAL) {
        const float* src; int off;
        if      (j < W_EX2) { src = ex1; off = W_EX1; }
        else if (j < W_EX3) { src = ex2; off = W_EX2; }
        else if (j < W_EZ1) { src = ex3; off = W_EX3; }
        else if (j < W_EZ2) { src = ez1; off = W_EZ1; }
        else if (j < W_EZ3) { src = ez2; off = W_EZ2; }
        else if (j < W_DE1) { src = ez3; off = W_EZ3; }
        else if (j < W_DE2) { src = de1; off = W_DE1; }
        else                { src = de2; off = W_DE2; }
        float4 v = reinterpret_cast<const float4*>(src)[(j - off) >> 2];
        __half2 a = __floats2half2_rn(v.x, v.y), b = __floats2half2_rn(v.z, v.w);
        uint2 u = { *reinterpret_cast<unsigned*>(&a), *reinterpret_cast<unsigned*>(&b) };
        *reinterpret_cast<uint2*>(&g_w16[j]) = u;
        return;
    }
    int sidx = i4 - NIN4 - W_TOTAL/4;
    if (sidx >= P_TOT) return;
    float v;
    if (sidx < P_AZT) {
        v = Wz[(sidx & 63)*64 + (sidx >> 6)];
    } else if (sidx < P_L) {
        int q = sidx - P_AZT;
        v = Azw[(q & 7)*64 + (q >> 3)];
    } else if (sidx < P_RT) {
        int q = sidx - P_L;
        int row = q / 12, col = q % 12;
        v = (col < 8) ? Lw[row*8 + col] : 0.f;
    } else if (sidx < P_AZB) {
        int q = sidx - P_RT;
        v = Rm[(q & 255)*8 + (q >> 8)];
    } else {
        v = Azb[sidx - P_AZB];
    }
    g_step[sidx] = v;
}

// ---------------------------------------------------------------------------
// Load a 128 x KH fp16 gmem tile into pitched smem (pitch = KH + 8)
// ---------------------------------------------------------------------------
template<int THREADS, int KH>
__device__ __forceinline__ void load_tile(const __half* __restrict__ g, __half* sDst)
{
    constexpr int AP = KH + 8;
    constexpr int CHT = 128 * KH / 8;
    const int tid = threadIdx.x;
    uint32_t d = (uint32_t)__cvta_generic_to_shared(sDst);
    #pragma unroll
    for (int c = tid; c < CHT; c += THREADS) {
        int row = c / (KH / 8), off = (c % (KH / 8)) * 8;
        cpa16(d + (uint32_t)((row * AP + off) * 2), g + (size_t)row * KH + off);
    }
    commitg(); waitg<0>(); __syncthreads();
}

// ---------------------------------------------------------------------------
// GEMM core: acc(128 x Nd) += smemA(128 x Kd, pitch Kd+8) @ gW(Nd x Kd)^T
// ---------------------------------------------------------------------------
template<int THREADS, int Nd, int Kd, int NT>
__device__ __forceinline__ void gemm_core(const __half* __restrict__ gW,
                                          const __half* sA, __half* sB,
                                          float (&acc)[2][NT][4])
{
    constexpr int BK = 32, NS = 4, BP = 40, AP = Kd + 8;
    constexpr int NWN = THREADS / 128;
    constexpr int WN = Nd / NWN;
    static_assert(NT == WN / 8, "NT mismatch");
    constexpr int S = Kd / BK;
    constexpr int CH = Nd * BK / 8;

    const int tid = threadIdx.x, lane = tid & 31, wid = tid >> 5;
    const int wm = wid & 3, wn = wid >> 2;
    const uint32_t aBase = (uint32_t)__cvta_generic_to_shared(sA);
    const uint32_t bBase = (uint32_t)__cvta_generic_to_shared(sB);
    const int arow = wm * 32 + (lane & 15);
    const int akof = (lane >> 4) << 3;
    const int brow = wn * WN + (lane & 7) + ((lane >> 4) << 3);
    const int bkof = ((lane >> 3) & 1) << 3;

    #pragma unroll
    for (int i = 0; i < 2; i++)
        #pragma unroll
        for (int j = 0; j < NT; j++)
            #pragma unroll
            for (int q = 0; q < 4; q++) acc[i][j][q] = 0.f;

    auto issueB = [&](int s, int slot) {
        #pragma unroll
        for (int c = tid; c < CH; c += THREADS) {
            int row = c >> 2, off = (c & 3) << 3;
            cpa16(bBase + (uint32_t)(((slot * Nd + row) * BP + off) * 2),
                  gW + (size_t)row * Kd + s * BK + off);
        }
    };

    #pragma unroll
    for (int i = 0; i < NS - 1; i++) { if (i < S) issueB(i, i); commitg(); }

    #pragma unroll
    for (int s = 0; s < S; s++) {
        waitg<NS - 2>();
        __syncthreads();
        if (s + NS - 1 < S) issueB(s + NS - 1, (s + NS - 1) & (NS - 1));
        commitg();
        const int slot = s & (NS - 1);
        #pragma unroll
        for (int kk = 0; kk < BK; kk += 16) {
            uint32_t af[2][4];
            uint32_t aa = aBase + (uint32_t)((arow * AP + s * BK + kk + akof) * 2);
            ldsm4(af[0], aa);
            ldsm4(af[1], aa + 16 * AP * 2);
            #pragma unroll
            for (int j2 = 0; j2 < NT / 2; j2++) {
                uint32_t bf[4];
                ldsm4(bf, bBase + (uint32_t)(((slot * Nd + brow + j2 * 16) * BP + kk + bkof) * 2));
                mma16816(acc[0][2 * j2],     af[0], bf[0], bf[1]);
                mma16816(acc[0][2 * j2 + 1], af[0], bf[2], bf[3]);
                mma16816(acc[1][2 * j2],     af[1], bf[0], bf[1]);
                mma16816(acc[1][2 * j2 + 1], af[1], bf[2], bf[3]);
            }
        }
    }
}

// ---------------------------------------------------------------------------
// Epilogue: ftanh(acc + bias) -> pitched smem (pitch Nd + 8)
// ---------------------------------------------------------------------------
template<int THREADS, int Nd, int NT>
__device__ __forceinline__ void epi_to_smem(float (&acc)[2][NT][4],
        const float* __restrict__ bias, __half* sOut)
{
    constexpr int NWN = THREADS / 128, WN = Nd / NWN, OP = Nd + 8;
    const int tid = threadIdx.x, lane = tid & 31, wid = tid >> 5;
    const int wm = wid & 3, wn = wid >> 2;
    const int g = lane >> 2, cq = (lane & 3) << 1;
    #pragma unroll
    for (int i = 0; i < 2; i++)
        #pragma unroll
        for (int h = 0; h < 2; h++) {
            const int row = wm * 32 + i * 16 + h * 8 + g;
            #pragma unroll
            for (int nt = 0; nt < NT; nt++) {
                const int col = wn * WN + nt * 8 + cq;
                float v0 = ftanh(acc[i][nt][2 * h + 0] + __ldg(bias + col));
                float v1 = ftanh(acc[i][nt][2 * h + 1] + __ldg(bias + col + 1));
                *reinterpret_cast<__half2*>(sOut + row * OP + col) =
                    __floats2half2_rn(v0, v1);
            }
        }
}

// ---------------------------------------------------------------------------
// fused_xz: per 128-row tile:
//   in16 -> ex1 ; in16 -> ez1 -> ez2 -> ez3 (z_seq + Z init)
//   ex1 -> ex2 -> ex3 (X init) -> de1 -> de2 -> x_rec
// z-chain activation buffers live in sA0's slack (in16 region dies after ez1).
// ---------------------------------------------------------------------------
__global__ void __launch_bounds__(512, 1)
fused_xz(const float* __restrict__ bx1, const float* __restrict__ bx2,
         const float* __restrict__ bx3, const float* __restrict__ bz1,
         const float* __restrict__ bz2, const float* __restrict__ bz3,
         const float* __restrict__ bd1, const float* __restrict__ bd2,
         float* __restrict__ x_rec, float* __restrict__ z_seq)
{
    extern __shared__ __half sm[];
    __half* sA0 = sm;                 // 33792 halfs
    __half* sA1 = sm + 33792;         // 33792 halfs
    __half* sB  = sm + 67584;         // 40960 halfs
    __half* zB0 = sA0 + 17408;        // 128x72, after in16 tile (128x136)
    __half* zB1 = sA0;                // 128x72, overwrites dead in16
    const int row0 = blockIdx.x * 128;
    const int tid = threadIdx.x, lane = tid & 31, wid = tid >> 5;
    const int wm = wid & 3, wn = wid >> 2;
    const int g = lane >> 2, cq = (lane & 3) << 1;

    load_tile<512, 128>(g_in16 + (size_t)row0 * PP, sA0);

    // ex1 (reads in16 tile in sA0, writes sA1)
    {   float acc[2][8][4];
        gemm_core<512, 256, 128, 8>(g_w16 + W_EX1, sA0, sB, acc);
        epi_to_smem<512, 256, 8>(acc, bx1, sA1);
    }
    __syncthreads();
    // ez1 (reads in16 tile in sA0, writes zB0)
    {   float acc[2][2][4];
        gemm_core<512, 64, 128, 2>(g_w16 + W_EZ1, sA0, sB, acc);
        epi_to_smem<512, 64, 2>(acc, bz1, zB0);
    }
    __syncthreads();
    // ez2 (zB0 -> zB1; in16 region now dead)
    {   float acc[2][2][4];
        gemm_core<512, 64, 64, 2>(g_w16 + W_EZ2, zB0, sB, acc);
        epi_to_smem<512, 64, 2>(acc, bz2, zB1);
    }
    __syncthreads();
    // ez3 -> z_seq fp32 + Z init
    {   float acc[2][2][4];
        gemm_core<512, 64, 64, 2>(g_w16 + W_EZ3, zB1, sB, acc);
        #pragma unroll
        for (int i = 0; i < 2; i++)
            #pragma unroll
            for (int h = 0; h < 2; h++) {
                const int row = wm * 32 + i * 16 + h * 8 + g;
                const int r = row0 + row;
                const int t = r & (TT - 1);
                const int rs = (t % 5 == 0) ? ((r >> 11) * CCH + t / 5) : -1;
                #pragma unroll
                for (int nt = 0; nt < 2; nt++) {
                    const int col = wn * 16 + nt * 8 + cq;
                    float v0 = ftanh(acc[i][nt][2 * h + 0] + __ldg(bz3 + col));
                    float v1 = ftanh(acc[i][nt][2 * h + 1] + __ldg(bz3 + col + 1));
                    *reinterpret_cast<float2*>(z_seq + (size_t)r * MM + col) =
                        make_float2(v0, v1);
                    if (rs >= 0)
                        *reinterpret_cast<float2*>(&g_Z[(size_t)rs * MM + col]) =
                            make_float2(v0, v1);
                }
            }
    }
    __syncthreads();
    // ex2 (sA1 -> sA0)
    {   float acc[2][8][4];
        gemm_core<512, 256, 256, 8>(g_w16 + W_EX2, sA1, sB, acc);
        epi_to_smem<512, 256, 8>(acc, bx2, sA0);
    }
    __syncthreads();
    // ex3 (sA0 -> sA1) + fp32 scan-state init
    {   float acc[2][8][4];
        gemm_core<512, 256, 256, 8>(g_w16 + W_EX3, sA0, sB, acc);
        #pragma unroll
        for (int i = 0; i < 2; i++)
            #pragma unroll
            for (int h = 0; h < 2; h++) {
                const int row = wm * 32 + i * 16 + h * 8 + g;
                const int r = row0 + row;
                const int t = r & (TT - 1);
                const int rs = (t % 5 == 0) ? ((r >> 11) * CCH + t / 5) : -1;
                #pragma unroll
                for (int nt = 0; nt < 8; nt++) {
                    const int col = wn * 64 + nt * 8 + cq;
                    float v0 = ftanh(acc[i][nt][2 * h + 0] + __ldg(bx3 + col));
                    float v1 = ftanh(acc[i][nt][2 * h + 1] + __ldg(bx3 + col + 1));
                    *reinterpret_cast<__half2*>(sA1 + row * 264 + col) =
                        __floats2half2_rn(v0, v1);
                    if (rs >= 0)
                        *reinterpret_cast<float2*>(&g_X[(size_t)rs * KK + col]) =
                            make_float2(v0, v1);
                }
            }
    }
    __syncthreads();
    // de1 (sA1 -> sA0)
    {   float acc[2][8][4];
        gemm_core<512, 256, 256, 8>(g_w16 + W_DE1, sA1, sB, acc);
        epi_to_smem<512, 256, 8>(acc, bd1, sA0);
    }
    __syncthreads();
    // de2 -> x_rec (fp32 dense)
    {   float acc[2][4][4];
        gemm_core<512, 128, 256, 4>(g_w16 + W_DE2, sA0, sB, acc);
        #pragma unroll
        for (int i = 0; i < 2; i++)
            #pragma unroll
            for (int h = 0; h < 2; h++) {
                const int row = wm * 32 + i * 16 + h * 8 + g;
                const int r = row0 + row;
                #pragma unroll
                for (int nt = 0; nt < 4; nt++) {
                    const int col = wn * 32 + nt * 8 + cq;
                    float v0 = ftanh(acc[i][nt][2 * h + 0] + __ldg(bd2 + col));
                    float v1 = ftanh(acc[i][nt][2 * h + 1] + __ldg(bd2 + col + 1));
                    *reinterpret_cast<float2*>(x_rec + (size_t)r * PP + col) =
                        make_float2(v0, v1);
                }
            }
    }
}

// ---------------------------------------------------------------------------
// mega_step: all 5 recurrence sub-steps; 4 rows per warp, state in registers.
// ---------------------------------------------------------------------------
__global__ void __launch_bounds__(256, 2)
mega_step(float* __restrict__ zpred)
{
    __shared__ __align__(16) float sP[P_TOT];
    __shared__ __align__(16) float stz[8][4][64];

    const int tid = threadIdx.x;
    for (int i = tid; i < P_TOT; i += 256) sP[i] = g_step[i];
    __syncthreads();
    const float*  sWzT = sP + P_WZT;
    const float*  sAzT = sP + P_AZT;
    const float4* sL4  = (const float4*)(sP + P_L);
    const float*  sRT  = sP + P_RT;
    const float*  sAzb = sP + P_AZB;

    const int w = tid >> 5, lane = tid & 31;
    const int r0 = (blockIdx.x * 8 + w) * 4;
    const int gr = lane >> 3, gq = lane & 7;

    int tbase[4]; size_t zoff[4];
    float zv0[4], zv1[4], xv[4][8];
    #pragma unroll
    for (int r = 0; r < 4; r++) {
        const int rr = r0 + r;
        const int b = rr / CCH, c = rr % CCH;
        tbase[r] = 5 * c;
        zoff[r]  = ((size_t)b * TT) * MM;
        zv0[r] = g_Z[(size_t)rr * MM + lane];
        zv1[r] = g_Z[(size_t)rr * MM + 32 + lane];
        #pragma unroll
        for (int k = 0; k < 8; k++)
            xv[r][k] = g_X[(size_t)rr * KK + lane + 32 * k];
    }

    #pragma unroll 1
    for (int s = 0; s < 5; s++) {
        #pragma unroll
        for (int r = 0; r < 4; r++) {
            stz[w][r][lane]      = htanh(zv0[r]);
            stz[w][r][lane + 32] = htanh(zv1[r]);
        }
        __syncwarp();
        float a0[4] = {0.f,0.f,0.f,0.f}, a1[4] = {0.f,0.f,0.f,0.f};
        #pragma unroll
        for (int i4 = 0; i4 < 16; i4++) {
            float4 tz[4];
            #pragma unroll
            for (int r = 0; r < 4; r++)
                tz[r] = *(const float4*)&stz[w][r][i4 * 4];
            const float* wr = sWzT + (i4 * 4) * 64 + lane;
            #pragma unroll
            for (int ii = 0; ii < 4; ii++) {
                const float w0 = wr[ii * 64], w1 = wr[ii * 64 + 32];
                const float c0 = (ii == 0) ? tz[0].x : (ii == 1) ? tz[0].y
                               : (ii == 2) ? tz[0].z : tz[0].w;
                const float c1 = (ii == 0) ? tz[1].x : (ii == 1) ? tz[1].y
                               : (ii == 2) ? tz[1].z : tz[1].w;
                const float c2 = (ii == 0) ? tz[2].x : (ii == 1) ? tz[2].y
                               : (ii == 2) ? tz[2].z : tz[2].w;
                const float c3 = (ii == 0) ? tz[3].x : (ii == 1) ? tz[3].y
                               : (ii == 2) ? tz[3].z : tz[3].w;
                a0[0] = fmaf(c0, w0, a0[0]);  a1[0] = fmaf(c0, w1, a1[0]);
                a0[1] = fmaf(c1, w0, a0[1]);  a1[1] = fmaf(c1, w1, a1[1]);
                a0[2] = fmaf(c2, w0, a0[2]);  a1[2] = fmaf(c2, w1, a1[2]);
                a0[3] = fmaf(c3, w0, a0[3]);  a1[3] = fmaf(c3, w1, a1[3]);
            }
        }
        #pragma unroll
        for (int r = 0; r < 4; r++) {
            zv0[r] = zv0[r] + (a0[r] - zv0[r]) * 0.01f;
            zv1[r] = zv1[r] + (a1[r] - zv1[r]) * 0.01f;
        }
        __syncwarp();
        #pragma unroll
        for (int r = 0; r < 4; r++) {
            stz[w][r][lane]      = zv0[r];
            stz[w][r][lane + 32] = zv1[r];
        }
        __syncwarp();
        float ga = 0.f;
        {
            const float* zr = stz[w][gr];
            #pragma unroll 8
            for (int i = 0; i < 64; i++)
                ga = fmaf(zr[i], sAzT[i * 8 + gq], ga);
        }
        const float sg = 1.f / (1.f + __expf(-(ga + sAzb[gq])));
        float gu[4][8];
        #pragma unroll
        for (int r = 0; r < 4; r++)
            #pragma unroll
            for (int q = 0; q < 8; q++) gu[r][q] = 0.f;
        #pragma unroll
        for (int k = 0; k < 8; k++) {
            const int j = lane + 32 * k;
            const float4 l0 = sL4[j * 3], l1 = sL4[j * 3 + 1];
            #pragma unroll
            for (int r = 0; r < 4; r++) {
                const float tx = htanh(xv[r][k]);
                gu[r][0] = fmaf(tx, l0.x, gu[r][0]);
                gu[r][1] = fmaf(tx, l0.y, gu[r][1]);
                gu[r][2] = fmaf(tx, l0.z, gu[r][2]);
                gu[r][3] = fmaf(tx, l0.w, gu[r][3]);
                gu[r][4] = fmaf(tx, l1.x, gu[r][4]);
                gu[r][5] = fmaf(tx, l1.y, gu[r][5]);
                gu[r][6] = fmaf(tx, l1.z, gu[r][6]);
                gu[r][7] = fmaf(tx, l1.w, gu[r][7]);
            }
        }
        #pragma unroll
        for (int off = 16; off > 0; off >>= 1)
            #pragma unroll
            for (int r = 0; r < 4; r++)
                #pragma unroll
                for (int q = 0; q < 8; q++)
                    gu[r][q] += __shfl_xor_sync(0xffffffffu, gu[r][q], off);
        #pragma unroll
        for (int r = 0; r < 4; r++)
            #pragma unroll
            for (int q = 0; q < 8; q++)
                gu[r][q] *= __shfl_sync(0xffffffffu, sg, r * 8 + q);
        #pragma unroll
        for (int k = 0; k < 8; k++) {
            const int j = lane + 32 * k;
            float acc[4] = {0.f,0.f,0.f,0.f};
            #pragma unroll
            for (int q = 0; q < 8; q++) {
                const float wv = sRT[q * 256 + j];
                acc[0] = fmaf(gu[0][q], wv, acc[0]);
                acc[1] = fmaf(gu[1][q], wv, acc[1]);
                acc[2] = fmaf(gu[2][q], wv, acc[2]);
                acc[3] = fmaf(gu[3][q], wv, acc[3]);
            }
            #pragma unroll
            for (int r = 0; r < 4; r++)
                xv[r][k] = xv[r][k] + (acc[r] - xv[r][k]) * 0.01f;
        }
        #pragma unroll
        for (int r = 0; r < 4; r++) {
            const int t = tbase[r] + s;
            if (t < TT) {
                float* zp = zpred + zoff[r] + (size_t)t * MM;
                zp[lane]      = zv0[r];
                zp[lane + 32] = zv1[r];
            }
            __half* xd = g_X16s + ((size_t)s * NRP + (r0 + r)) * KK;
            #pragma unroll
            for (int k = 0; k < 8; k++)
                xd[lane + 32 * k] = __float2half(xv[r][k]);
        }
    }
}

// ---------------------------------------------------------------------------
// fused_dec: one launch over all 5 steps x NRP rows: X16s -> de1 -> de2 -> x_pred
// ---------------------------------------------------------------------------
__global__ void __launch_bounds__(512, 1)
fused_dec(const float* __restrict__ bd1, const float* __restrict__ bd2,
          float* __restrict__ x_pred)
{
    extern __shared__ __half sm[];
    __half* sA0 = sm;
    __half* sA1 = sm + 33792;
    __half* sB  = sm + 67584;
    const int s    = blockIdx.x / (NRP / 128);
    const int row0 = (blockIdx.x % (NRP / 128)) * 128;
    const int tid = threadIdx.x, lane = tid & 31, wid = tid >> 5;
    const int wm = wid & 3, wn = wid >> 2;
    const int g = lane >> 2, cq = (lane & 3) << 1;

    load_tile<512, 256>(g_X16s + ((size_t)s * NRP + row0) * KK, sA0);

    {   float acc[2][8][4];
        gemm_core<512, 256, 256, 8>(g_w16 + W_DE1, sA0, sB, acc);
        epi_to_smem<512, 256, 8>(acc, bd1, sA1);
    }
    __syncthreads();
    {   float acc[2][4][4];
        gemm_core<512, 128, 256, 4>(g_w16 + W_DE2, sA1, sB, acc);
        #pragma unroll
        for (int i = 0; i < 2; i++)
            #pragma unroll
            for (int h = 0; h < 2; h++) {
                const int row = wm * 32 + i * 16 + h * 8 + g;
                const int r = row0 + row;
                if (r >= NR) continue;
                const int b = r / CCH, c = r % CCH;
                const int t = 5 * c + s;
                if (t >= TT) continue;
                float* crow = x_pred + ((size_t)b * TT + t) * PP;
                #pragma unroll
                for (int nt = 0; nt < 4; nt++) {
                    const int col = wn * 32 + nt * 8 + cq;
                    float v0 = ftanh(acc[i][nt][2 * h + 0] + __ldg(bd2 + col));
                    float v1 = ftanh(acc[i][nt][2 * h + 1] + __ldg(bd2 + col + 1));
                    *reinterpret_cast<float2*>(crow + col) = make_float2(v0, v1);
                }
            }
    }
}

// ---------------------------------------------------------------------------
extern "C" void kernel_launch(void* const* d_in, const int* in_sizes, int n_in,
                              void* d_out, int out_size)
{
    (void)in_sizes; (void)n_in; (void)out_size;
    const float* in_seq = (const float*)d_in[0];
    const float* L      = (const float*)d_in[1];
    const float* Rm     = (const float*)d_in[2];
    const float* Wz     = (const float*)d_in[3];
    const float* Az_w   = (const float*)d_in[4];
    const float* Az_b   = (const float*)d_in[5];
    const float* ex1_w  = (const float*)d_in[6];
    const float* ex1_b  = (const float*)d_in[7];
    const float* ex2_w  = (const float*)d_in[8];
    const float* ex2_b  = (const float*)d_in[9];
    const float* ex3_w  = (const float*)d_in[10];
    const float* ex3_b  = (const float*)d_in[11];
    const float* ez1_w  = (const float*)d_in[12];
    const float* ez1_b  = (const float*)d_in[13];
    const float* ez2_w  = (const float*)d_in[14];
    const float* ez2_b  = (const float*)d_in[15];
    const float* ez3_w  = (const float*)d_in[16];
    const float* ez3_b  = (const float*)d_in[17];
    const float* de1_w  = (const float*)d_in[18];
    const float* de1_b  = (const float*)d_in[19];
    const float* de2_w  = (const float*)d_in[20];
    const float* de2_b  = (const float*)d_in[21];

    float* out    = (float*)d_out;
    float* x_pred = out;
    float* x_rec  = out + (size_t)BB*TT*PP;
    float* z_pred = out + 2*(size_t)BB*TT*PP;
    float* z_seq  = z_pred + (size_t)BB*TT*MM;

    const int SMX = (2 * 128 * 264 + 4 * 256 * 40) * 2;   // 217088 B
    cudaFuncSetAttribute(fused_xz,  cudaFuncAttributeMaxDynamicSharedMemorySize, SMX);
    cudaFuncSetAttribute(fused_dec, cudaFuncAttributeMaxDynamicSharedMemorySize, SMX);

    // 1. conversions + step-weight transposes
    {
        const int TOT = NROWS*PP/4 + W_TOTAL/4 + P_TOT;
        conv_kernel<<<(TOT + 255) / 256, 256>>>(in_seq, ex1_w, ex2_w, ex3_w,
                                                ez1_w, ez2_w, ez3_w, de1_w, de2_w,
                                                Wz, Az_w, Az_b, L, Rm);
    }

    // 2. fully fused encoder/decoder chain (x + z) — seeds scan state too
    fused_xz<<<NROWS/128, 512, SMX>>>(ex1_b, ex2_b, ex3_b,
                                      ez1_b, ez2_b, ez3_b,
                                      de1_b, de2_b, x_rec, z_seq);

    // 3. all 5 recurrence sub-steps in one launch (4 rows/warp)
    mega_step<<<NR/32, 256>>>(z_pred);

    // 4. one decoder launch over all 5 step snapshots
    fused_dec<<<5 * (NRP/128), 512, SMX>>>(de1_b, de2_b, x_pred);
}